// round 1
// baseline (speedup 1.0000x reference)
#include <cuda_runtime.h>
#include <cuda_bf16.h>
#include <math.h>

#define L_  12
#define NH_ 12
#define DH_ 64
#define H_  768
#define FF_ 3072
#define S_  1024
#define B_  4
#define BS_ (B_ * S_)   // 4096
#define WIN_ 256

// ---------------- scratch (no allocations allowed) ----------------
__device__ float g_h  [BS_ * H_];
__device__ float g_q  [BS_ * H_];
__device__ float g_k  [BS_ * H_];
__device__ float g_v  [BS_ * H_];
__device__ float g_a  [BS_ * H_];
__device__ float g_ffn[BS_ * FF_];
__device__ float g_sc [BS_];
__device__ float g_pr [BS_];
__device__ float g_pool[B_ * H_];

// ---------------- reduction helpers ----------------
__device__ __forceinline__ float block_reduce_sum(float v) {
    __shared__ float red[32];
    int lane = threadIdx.x & 31, wid = threadIdx.x >> 5;
    #pragma unroll
    for (int o = 16; o; o >>= 1) v += __shfl_xor_sync(0xffffffffu, v, o);
    if (lane == 0) red[wid] = v;
    __syncthreads();
    int nw = (blockDim.x + 31) >> 5;
    v = (threadIdx.x < nw) ? red[threadIdx.x] : 0.f;
    if (wid == 0) {
        #pragma unroll
        for (int o = 16; o; o >>= 1) v += __shfl_xor_sync(0xffffffffu, v, o);
    }
    if (threadIdx.x == 0) red[0] = v;
    __syncthreads();
    v = red[0];
    __syncthreads();
    return v;
}

__device__ __forceinline__ float block_reduce_max(float v) {
    __shared__ float red[32];
    int lane = threadIdx.x & 31, wid = threadIdx.x >> 5;
    #pragma unroll
    for (int o = 16; o; o >>= 1) v = fmaxf(v, __shfl_xor_sync(0xffffffffu, v, o));
    if (lane == 0) red[wid] = v;
    __syncthreads();
    int nw = (blockDim.x + 31) >> 5;
    v = (threadIdx.x < nw) ? red[threadIdx.x] : -1e30f;
    if (wid == 0) {
        #pragma unroll
        for (int o = 16; o; o >>= 1) v = fmaxf(v, __shfl_xor_sync(0xffffffffu, v, o));
    }
    if (threadIdx.x == 0) red[0] = v;
    __syncthreads();
    v = red[0];
    __syncthreads();
    return v;
}

// ---------------- embedding + LN ----------------
__global__ __launch_bounds__(256) void embed_ln_kernel(
    const float* __restrict__ WE, const float* __restrict__ PE,
    const float* __restrict__ g, const float* __restrict__ be,
    const int* __restrict__ ids, float* __restrict__ out)
{
    int t = blockIdx.x;            // token 0..4095
    int s = t & (S_ - 1);
    int tid = threadIdx.x;
    int id = ids[t];
    float v[3];
    #pragma unroll
    for (int i = 0; i < 3; i++) {
        int c = tid + i * 256;
        v[i] = WE[(size_t)id * H_ + c] + PE[(size_t)s * H_ + c];
    }
    float ssum = block_reduce_sum(v[0] + v[1] + v[2]);
    float m = ssum * (1.f / H_);
    float sq = 0.f;
    #pragma unroll
    for (int i = 0; i < 3; i++) { float d = v[i] - m; sq += d * d; }
    float vs = block_reduce_sum(sq);
    float rs = rsqrtf(vs * (1.f / H_) + 1e-5f);
    #pragma unroll
    for (int i = 0; i < 3; i++) {
        int c = tid + i * 256;
        out[(size_t)t * H_ + c] = (v[i] - m) * rs * g[c] + be[c];
    }
}

// ---------------- residual add + LN (in-place on h) ----------------
__global__ __launch_bounds__(256) void add_ln_kernel(
    float* __restrict__ h, const float* __restrict__ r,
    const float* __restrict__ g, const float* __restrict__ be)
{
    int t = blockIdx.x;
    int tid = threadIdx.x;
    float v[3];
    #pragma unroll
    for (int i = 0; i < 3; i++) {
        int c = tid + i * 256;
        v[i] = h[(size_t)t * H_ + c] + r[(size_t)t * H_ + c];
    }
    float ssum = block_reduce_sum(v[0] + v[1] + v[2]);
    float m = ssum * (1.f / H_);
    float sq = 0.f;
    #pragma unroll
    for (int i = 0; i < 3; i++) { float d = v[i] - m; sq += d * d; }
    float vs = block_reduce_sum(sq);
    float rs = rsqrtf(vs * (1.f / H_) + 1e-5f);
    #pragma unroll
    for (int i = 0; i < 3; i++) {
        int c = tid + i * 256;
        h[(size_t)t * H_ + c] = (v[i] - m) * rs * g[c] + be[c];
    }
}

// ---------------- SGEMM: C[M,N] = A[M,K] @ W[K,N] + bias, optional GELU ----
// block 256 threads, 128x128 tile, BK=8, 8x8 per thread
__global__ __launch_bounds__(256) void sgemm_kernel(
    const float* __restrict__ A, const float* __restrict__ W,
    const float* __restrict__ bias, float* __restrict__ C,
    int M, int N, int K, int act)
{
    __shared__ float As[8][128];
    __shared__ float Bs[8][128];
    const int tid = threadIdx.x;
    const int m0 = blockIdx.y * 128;
    const int n0 = blockIdx.x * 128;
    const int tx = tid & 15, ty = tid >> 4;

    float acc[8][8];
    #pragma unroll
    for (int i = 0; i < 8; i++)
        #pragma unroll
        for (int j = 0; j < 8; j++) acc[i][j] = 0.f;

    const int arow = tid >> 1;            // 0..127
    const int acol = (tid & 1) * 4;       // 0 or 4
    const int brow = tid >> 5;            // 0..7
    const int bcol = (tid & 31) * 4;      // 0..124

    for (int k0 = 0; k0 < K; k0 += 8) {
        float4 av = *(const float4*)(A + (size_t)(m0 + arow) * K + k0 + acol);
        As[acol + 0][arow] = av.x;
        As[acol + 1][arow] = av.y;
        As[acol + 2][arow] = av.z;
        As[acol + 3][arow] = av.w;
        float4 bv = *(const float4*)(W + (size_t)(k0 + brow) * N + n0 + bcol);
        *(float4*)&Bs[brow][bcol] = bv;
        __syncthreads();
        #pragma unroll
        for (int kk = 0; kk < 8; kk++) {
            float af[8], bf[8];
            #pragma unroll
            for (int i = 0; i < 8; i++) af[i] = As[kk][ty * 8 + i];
            #pragma unroll
            for (int j = 0; j < 8; j++) bf[j] = Bs[kk][tx * 8 + j];
            #pragma unroll
            for (int i = 0; i < 8; i++)
                #pragma unroll
                for (int j = 0; j < 8; j++) acc[i][j] += af[i] * bf[j];
        }
        __syncthreads();
    }

    #pragma unroll
    for (int i = 0; i < 8; i++) {
        int row = m0 + ty * 8 + i;
        #pragma unroll
        for (int j = 0; j < 8; j++) {
            int col = n0 + tx * 8 + j;
            float v = acc[i][j] + bias[col];
            if (act == 1) v = 0.5f * v * (1.0f + erff(v * 0.70710678118654752f));
            C[(size_t)row * N + col] = v;
        }
    }
}

// ---------------- local (banded) attention, flash-style ----------------
// grid: (S/64, NH, B), 256 threads. Query tile 64, key tile 64, DH=64.
__global__ __launch_bounds__(256) void local_attn_kernel(
    const float* __restrict__ Q, const float* __restrict__ K,
    const float* __restrict__ V, const int* __restrict__ amask,
    float* __restrict__ O)
{
    __shared__ float Qs[64][65];
    __shared__ float KVs[64][65];
    const int q0 = blockIdx.x * 64;
    const int hh = blockIdx.y;
    const int b  = blockIdx.z;
    const int tid = threadIdx.x;
    const int tx = tid & 15, ty = tid >> 4;
    const unsigned FULL = 0xffffffffu;

    // load Q tile
    for (int idx = tid; idx < 64 * 64; idx += 256) {
        int r = idx >> 6, d = idx & 63;
        Qs[r][d] = Q[((size_t)(b * S_ + q0 + r)) * H_ + hh * DH_ + d];
    }

    float m[4], lsum[4], acc[4][4];
    #pragma unroll
    for (int i = 0; i < 4; i++) {
        m[i] = -1e30f; lsum[i] = 0.f;
        #pragma unroll
        for (int j = 0; j < 4; j++) acc[i][j] = 0.f;
    }

    for (int kt = 0; kt < 9; kt++) {
        const int ks = q0 - 256 + kt * 64;
        if (ks + 64 <= 0 || ks >= S_) continue;   // uniform per block
        __syncthreads();  // protect KVs (prev iter) and Qs (first iter)
        for (int idx = tid; idx < 64 * 64; idx += 256) {
            int c = idx >> 6, d = idx & 63;
            int kg = ks + c;
            KVs[c][d] = (kg >= 0 && kg < S_)
                ? K[((size_t)(b * S_ + kg)) * H_ + hh * DH_ + d] : 0.f;
        }
        __syncthreads();

        // scores: 4x4 per thread
        float s[4][4];
        #pragma unroll
        for (int i = 0; i < 4; i++)
            #pragma unroll
            for (int j = 0; j < 4; j++) s[i][j] = 0.f;
        #pragma unroll 8
        for (int d = 0; d < 64; d++) {
            float qv[4], kv[4];
            #pragma unroll
            for (int rr = 0; rr < 4; rr++) qv[rr] = Qs[ty * 4 + rr][d];
            #pragma unroll
            for (int cc = 0; cc < 4; cc++) kv[cc] = KVs[tx * 4 + cc][d];
            #pragma unroll
            for (int rr = 0; rr < 4; rr++)
                #pragma unroll
                for (int cc = 0; cc < 4; cc++) s[rr][cc] += qv[rr] * kv[cc];
        }

        // mask + online softmax
        float p[4][4];
        #pragma unroll
        for (int rr = 0; rr < 4; rr++) {
            int qg = q0 + ty * 4 + rr;
            float sv[4];
            float tmax = -1e30f;
            #pragma unroll
            for (int cc = 0; cc < 4; cc++) {
                int kg = ks + tx * 4 + cc;
                int delta = kg - qg;
                bool ok = (kg >= 0) && (kg < S_) && (delta >= -WIN_) && (delta <= WIN_)
                          && (amask[b * S_ + kg] > 0);
                sv[cc] = ok ? s[rr][cc] * 0.125f : -1e9f;
                tmax = fmaxf(tmax, sv[cc]);
            }
            #pragma unroll
            for (int o = 8; o; o >>= 1)
                tmax = fmaxf(tmax, __shfl_xor_sync(FULL, tmax, o, 16));
            float mn = fmaxf(m[rr], tmax);
            float scale = __expf(m[rr] - mn);
            float psum = 0.f;
            #pragma unroll
            for (int cc = 0; cc < 4; cc++) {
                p[rr][cc] = __expf(sv[cc] - mn);
                psum += p[rr][cc];
            }
            #pragma unroll
            for (int o = 8; o; o >>= 1)
                psum += __shfl_xor_sync(FULL, psum, o, 16);
            lsum[rr] = lsum[rr] * scale + psum;
            #pragma unroll
            for (int dd = 0; dd < 4; dd++) acc[rr][dd] *= scale;
            m[rr] = mn;
        }

        // swap in V tile
        __syncthreads();
        for (int idx = tid; idx < 64 * 64; idx += 256) {
            int c = idx >> 6, d = idx & 63;
            int kg = ks + c;
            KVs[c][d] = (kg >= 0 && kg < S_)
                ? V[((size_t)(b * S_ + kg)) * H_ + hh * DH_ + d] : 0.f;
        }
        __syncthreads();

        // O += P @ V   (p broadcast via width-16 shuffles)
        for (int jj = 0; jj < 64; jj += 4) {
            const int src = jj >> 2;
            #pragma unroll
            for (int cc = 0; cc < 4; cc++) {
                const int j = jj + cc;
                float vv0 = KVs[j][tx * 4 + 0];
                float vv1 = KVs[j][tx * 4 + 1];
                float vv2 = KVs[j][tx * 4 + 2];
                float vv3 = KVs[j][tx * 4 + 3];
                #pragma unroll
                for (int rr = 0; rr < 4; rr++) {
                    float pj = __shfl_sync(FULL, p[rr][cc], src, 16);
                    acc[rr][0] += pj * vv0;
                    acc[rr][1] += pj * vv1;
                    acc[rr][2] += pj * vv2;
                    acc[rr][3] += pj * vv3;
                }
            }
        }
    }

    #pragma unroll
    for (int rr = 0; rr < 4; rr++) {
        float inv = 1.f / lsum[rr];
        int qg = q0 + ty * 4 + rr;
        #pragma unroll
        for (int dd = 0; dd < 4; dd++) {
            O[((size_t)(b * S_ + qg)) * H_ + hh * DH_ + tx * 4 + dd] = acc[rr][dd] * inv;
        }
    }
}

// ---------------- pooling head ----------------
__global__ __launch_bounds__(256) void attn_score_kernel(
    const float* __restrict__ h, const float* __restrict__ aw, float* __restrict__ sc)
{
    int t = blockIdx.x;
    int tid = threadIdx.x;
    float acc = 0.f;
    #pragma unroll
    for (int i = 0; i < 3; i++) {
        int c = tid + i * 256;
        acc += h[(size_t)t * H_ + c] * aw[c];
    }
    float s = block_reduce_sum(acc);
    if (tid == 0) sc[t] = s;
}

__global__ __launch_bounds__(256) void softmax_s_kernel(
    const float* __restrict__ sc, float* __restrict__ pr)
{
    int b = blockIdx.x;
    int tid = threadIdx.x;
    float v[4];
    float mx = -1e30f;
    #pragma unroll
    for (int i = 0; i < 4; i++) {
        v[i] = sc[b * S_ + tid + i * 256];
        mx = fmaxf(mx, v[i]);
    }
    mx = block_reduce_max(mx);
    float e[4], ps = 0.f;
    #pragma unroll
    for (int i = 0; i < 4; i++) { e[i] = __expf(v[i] - mx); ps += e[i]; }
    float tot = block_reduce_sum(ps);
    float inv = 1.f / tot;
    #pragma unroll
    for (int i = 0; i < 4; i++) pr[b * S_ + tid + i * 256] = e[i] * inv;
}

__global__ __launch_bounds__(256) void pool_kernel(
    const float* __restrict__ h, const float* __restrict__ pr, float* __restrict__ pooled)
{
    int d = blockIdx.x * 256 + threadIdx.x;   // 0..767
    int b = blockIdx.y;
    float acc = 0.f;
    for (int s = 0; s < S_; s++) {
        acc += h[((size_t)(b * S_ + s)) * H_ + d] * pr[b * S_ + s];
    }
    pooled[b * H_ + d] = acc;
}

__global__ __launch_bounds__(256) void final_kernel(
    const float* __restrict__ pooled, const float* __restrict__ Wc,
    const float* __restrict__ bc, float* __restrict__ out)
{
    int b = blockIdx.x;
    int tid = threadIdx.x;
    float acc = 0.f;
    #pragma unroll
    for (int i = 0; i < 3; i++) {
        int c = tid + i * 256;
        acc += pooled[b * H_ + c] * Wc[c];
    }
    float s = block_reduce_sum(acc);
    if (tid == 0) out[b] = s + bc[0];
}

// ---------------- host launcher ----------------
extern "C" void kernel_launch(void* const* d_in, const int* in_sizes, int n_in,
                              void* d_out, int out_size)
{
    (void)in_sizes; (void)n_in; (void)out_size;
    const float* WE   = (const float*)d_in[0];
    const float* PE   = (const float*)d_in[1];
    const float* Eg   = (const float*)d_in[2];
    const float* Eb   = (const float*)d_in[3];
    const float* Wq   = (const float*)d_in[4];
    const float* bq   = (const float*)d_in[5];
    const float* Wk   = (const float*)d_in[6];
    const float* bk   = (const float*)d_in[7];
    const float* Wv   = (const float*)d_in[8];
    const float* bv   = (const float*)d_in[9];
    const float* Wo   = (const float*)d_in[10];
    const float* bo   = (const float*)d_in[11];
    const float* g1   = (const float*)d_in[12];
    const float* beta1= (const float*)d_in[13];
    const float* W1   = (const float*)d_in[14];
    const float* b1   = (const float*)d_in[15];
    const float* W2   = (const float*)d_in[16];
    const float* b2   = (const float*)d_in[17];
    const float* g2   = (const float*)d_in[18];
    const float* beta2= (const float*)d_in[19];
    const float* aw   = (const float*)d_in[20];
    const float* Wc   = (const float*)d_in[21];
    const float* bc   = (const float*)d_in[22];
    const int*   ids  = (const int*)d_in[23];
    const int*   am   = (const int*)d_in[24];
    float* out = (float*)d_out;

    float *h, *q, *k, *v, *a, *ffn, *sc, *pr, *pooled;
    cudaGetSymbolAddress((void**)&h,   g_h);
    cudaGetSymbolAddress((void**)&q,   g_q);
    cudaGetSymbolAddress((void**)&k,   g_k);
    cudaGetSymbolAddress((void**)&v,   g_v);
    cudaGetSymbolAddress((void**)&a,   g_a);
    cudaGetSymbolAddress((void**)&ffn, g_ffn);
    cudaGetSymbolAddress((void**)&sc,  g_sc);
    cudaGetSymbolAddress((void**)&pr,  g_pr);
    cudaGetSymbolAddress((void**)&pooled, g_pool);

    embed_ln_kernel<<<BS_, 256>>>(WE, PE, Eg, Eb, ids, h);

    dim3 g768(H_ / 128, BS_ / 128);    // (6, 32)
    dim3 g3072(FF_ / 128, BS_ / 128);  // (24, 32)
    dim3 gattn(S_ / 64, NH_, B_);      // (16, 12, 4)

    for (int l = 0; l < L_; l++) {
        const float* Wq_l = Wq + (size_t)l * H_ * H_;
        const float* Wk_l = Wk + (size_t)l * H_ * H_;
        const float* Wv_l = Wv + (size_t)l * H_ * H_;
        const float* Wo_l = Wo + (size_t)l * H_ * H_;
        const float* W1_l = W1 + (size_t)l * H_ * FF_;
        const float* W2_l = W2 + (size_t)l * FF_ * H_;

        sgemm_kernel<<<g768, 256>>>(h, Wq_l, bq + l * H_, q, BS_, H_, H_, 0);
        sgemm_kernel<<<g768, 256>>>(h, Wk_l, bk + l * H_, k, BS_, H_, H_, 0);
        sgemm_kernel<<<g768, 256>>>(h, Wv_l, bv + l * H_, v, BS_, H_, H_, 0);

        local_attn_kernel<<<gattn, 256>>>(q, k, v, am, a);

        sgemm_kernel<<<g768, 256>>>(a, Wo_l, bo + l * H_, q, BS_, H_, H_, 0);
        add_ln_kernel<<<BS_, 256>>>(h, q, g1 + l * H_, beta1 + l * H_);

        sgemm_kernel<<<g3072, 256>>>(h, W1_l, b1 + l * FF_, ffn, BS_, FF_, H_, 1);
        sgemm_kernel<<<g768, 256>>>(ffn, W2_l, b2 + l * H_, q, BS_, H_, FF_, 0);
        add_ln_kernel<<<BS_, 256>>>(h, q, g2 + l * H_, beta2 + l * H_);
    }

    attn_score_kernel<<<BS_, 256>>>(h, aw, sc);
    softmax_s_kernel<<<B_, 256>>>(sc, pr);
    pool_kernel<<<dim3(H_ / 256, B_), 256>>>(h, pr, pooled);
    final_kernel<<<B_, 256>>>(pooled, Wc, bc, out);
}

// round 4
// speedup vs baseline: 1.2523x; 1.2523x over previous
#include <cuda_runtime.h>
#include <cuda_bf16.h>
#include <cstdint>
#include <math.h>

#define L_  12
#define NH_ 12
#define DH_ 64
#define H_  768
#define FF_ 3072
#define S_  1024
#define B_  4
#define BS_ (B_ * S_)   // 4096
#define WIN_ 256

// ---------------- scratch (no allocations allowed) ----------------
__device__ float g_h  [BS_ * H_];
__device__ float g_q  [BS_ * H_];
__device__ float g_k  [BS_ * H_];
__device__ float g_v  [BS_ * H_];
__device__ float g_a  [BS_ * H_];
__device__ float g_ffn[BS_ * FF_];
__device__ float g_sc [BS_];
__device__ float g_pr [BS_];
__device__ float g_pool[B_ * H_];

// ---------------- reduction helpers ----------------
__device__ __forceinline__ float block_reduce_sum(float v) {
    __shared__ float red[32];
    int lane = threadIdx.x & 31, wid = threadIdx.x >> 5;
    #pragma unroll
    for (int o = 16; o; o >>= 1) v += __shfl_xor_sync(0xffffffffu, v, o);
    if (lane == 0) red[wid] = v;
    __syncthreads();
    int nw = (blockDim.x + 31) >> 5;
    v = (threadIdx.x < nw) ? red[threadIdx.x] : 0.f;
    if (wid == 0) {
        #pragma unroll
        for (int o = 16; o; o >>= 1) v += __shfl_xor_sync(0xffffffffu, v, o);
    }
    if (threadIdx.x == 0) red[0] = v;
    __syncthreads();
    v = red[0];
    __syncthreads();
    return v;
}

__device__ __forceinline__ float block_reduce_max(float v) {
    __shared__ float red[32];
    int lane = threadIdx.x & 31, wid = threadIdx.x >> 5;
    #pragma unroll
    for (int o = 16; o; o >>= 1) v = fmaxf(v, __shfl_xor_sync(0xffffffffu, v, o));
    if (lane == 0) red[wid] = v;
    __syncthreads();
    int nw = (blockDim.x + 31) >> 5;
    v = (threadIdx.x < nw) ? red[threadIdx.x] : -1e30f;
    if (wid == 0) {
        #pragma unroll
        for (int o = 16; o; o >>= 1) v = fmaxf(v, __shfl_xor_sync(0xffffffffu, v, o));
    }
    if (threadIdx.x == 0) red[0] = v;
    __syncthreads();
    v = red[0];
    __syncthreads();
    return v;
}

// ---------------- embedding + LN ----------------
__global__ __launch_bounds__(256) void embed_ln_kernel(
    const float* __restrict__ WE, const float* __restrict__ PE,
    const float* __restrict__ g, const float* __restrict__ be,
    const int* __restrict__ ids, float* __restrict__ out)
{
    int t = blockIdx.x;            // token 0..4095
    int s = t & (S_ - 1);
    int tid = threadIdx.x;
    int id = ids[t];
    float v[3];
    #pragma unroll
    for (int i = 0; i < 3; i++) {
        int c = tid + i * 256;
        v[i] = WE[(size_t)id * H_ + c] + PE[(size_t)s * H_ + c];
    }
    float ssum = block_reduce_sum(v[0] + v[1] + v[2]);
    float m = ssum * (1.f / H_);
    float sq = 0.f;
    #pragma unroll
    for (int i = 0; i < 3; i++) { float d = v[i] - m; sq += d * d; }
    float vs = block_reduce_sum(sq);
    float rs = rsqrtf(vs * (1.f / H_) + 1e-5f);
    #pragma unroll
    for (int i = 0; i < 3; i++) {
        int c = tid + i * 256;
        out[(size_t)t * H_ + c] = (v[i] - m) * rs * g[c] + be[c];
    }
}

// ---------------- residual add + LN (in-place on h) ----------------
__global__ __launch_bounds__(256) void add_ln_kernel(
    float* __restrict__ h, const float* __restrict__ r,
    const float* __restrict__ g, const float* __restrict__ be)
{
    int t = blockIdx.x;
    int tid = threadIdx.x;
    float v[3];
    #pragma unroll
    for (int i = 0; i < 3; i++) {
        int c = tid + i * 256;
        v[i] = h[(size_t)t * H_ + c] + r[(size_t)t * H_ + c];
    }
    float ssum = block_reduce_sum(v[0] + v[1] + v[2]);
    float m = ssum * (1.f / H_);
    float sq = 0.f;
    #pragma unroll
    for (int i = 0; i < 3; i++) { float d = v[i] - m; sq += d * d; }
    float vs = block_reduce_sum(sq);
    float rs = rsqrtf(vs * (1.f / H_) + 1e-5f);
    #pragma unroll
    for (int i = 0; i < 3; i++) {
        int c = tid + i * 256;
        h[(size_t)t * H_ + c] = (v[i] - m) * rs * g[c] + be[c];
    }
}

// ================= 3xTF32 tensor-core GEMM (fp32-accurate) =================
// C[M,N] = A[M,K] @ W[K,N] + bias, optional GELU.
// 128x128 block tile, BK=16, 8 warps (4x2), warp tile 32x64.
// Each operand split a = a_hi + a_lo (both tf32); product via 3 MMAs.

#define AS_STRIDE 20    // 16 + pad 4 -> conflict-free a-frag loads
#define BS_STRIDE 136   // 128 + pad 8 -> conflict-free b-frag loads

__device__ __forceinline__ void cp_async16(uint32_t smem_addr, const void* gptr) {
    asm volatile("cp.async.cg.shared.global [%0], [%1], 16;\n"
                 :: "r"(smem_addr), "l"(gptr));
}
__device__ __forceinline__ void cp_async_commit() {
    asm volatile("cp.async.commit_group;\n");
}
__device__ __forceinline__ void cp_async_wait0() {
    asm volatile("cp.async.wait_group 0;\n");
}
__device__ __forceinline__ uint32_t f2tf32(float f) {
    uint32_t u;
    asm("cvt.rna.tf32.f32 %0, %1;" : "=r"(u) : "f"(f));
    return u;
}
__device__ __forceinline__ void mma_tf32(
    float* acc, uint32_t a0, uint32_t a1, uint32_t a2, uint32_t a3,
    uint32_t b0, uint32_t b1)
{
    asm volatile(
        "mma.sync.aligned.m16n8k8.row.col.f32.tf32.tf32.f32 "
        "{%0,%1,%2,%3}, {%4,%5,%6,%7}, {%8,%9}, {%0,%1,%2,%3};\n"
        : "+f"(acc[0]), "+f"(acc[1]), "+f"(acc[2]), "+f"(acc[3])
        : "r"(a0), "r"(a1), "r"(a2), "r"(a3), "r"(b0), "r"(b1));
}

__global__ __launch_bounds__(256) void tgemm_kernel(
    const float* __restrict__ A, const float* __restrict__ W,
    const float* __restrict__ bias, float* __restrict__ C,
    int M, int N, int K, int act)
{
    __shared__ float As[2][128][AS_STRIDE];
    __shared__ float Bs[2][16][BS_STRIDE];

    const int tid  = threadIdx.x;
    const int warp = tid >> 5;
    const int lane = tid & 31;
    const int m0 = blockIdx.y * 128;
    const int n0 = blockIdx.x * 128;
    const int wm = (warp >> 1) * 32;   // warp row offset in tile
    const int wn = (warp & 1) * 64;    // warp col offset in tile

    const int grp = lane >> 2;         // 0..7
    const int tig = lane & 3;          // 0..3

    float acc[2][8][4];
    #pragma unroll
    for (int mi = 0; mi < 2; mi++)
        #pragma unroll
        for (int ni = 0; ni < 8; ni++)
            #pragma unroll
            for (int c = 0; c < 4; c++) acc[mi][ni][c] = 0.f;

    const int KT = K >> 4;

    // ---- issue load for stage 0 ----
    {
        #pragma unroll
        for (int r = 0; r < 2; r++) {
            int idx = tid + r * 256;
            int row = idx >> 2, cg = idx & 3;
            uint32_t dst = (uint32_t)__cvta_generic_to_shared(&As[0][row][cg * 4]);
            cp_async16(dst, A + (size_t)(m0 + row) * K + cg * 4);
        }
        #pragma unroll
        for (int r = 0; r < 2; r++) {
            int idx = tid + r * 256;
            int krow = idx >> 5, cg = idx & 31;
            uint32_t dst = (uint32_t)__cvta_generic_to_shared(&Bs[0][krow][cg * 4]);
            cp_async16(dst, W + (size_t)krow * N + n0 + cg * 4);
        }
        cp_async_commit();
    }

    int buf = 0;
    for (int kt = 0; kt < KT; kt++) {
        cp_async_wait0();
        __syncthreads();

        // prefetch next stage
        if (kt + 1 < KT) {
            const int k0 = (kt + 1) << 4;
            const int nb = buf ^ 1;
            #pragma unroll
            for (int r = 0; r < 2; r++) {
                int idx = tid + r * 256;
                int row = idx >> 2, cg = idx & 3;
                uint32_t dst = (uint32_t)__cvta_generic_to_shared(&As[nb][row][cg * 4]);
                cp_async16(dst, A + (size_t)(m0 + row) * K + k0 + cg * 4);
            }
            #pragma unroll
            for (int r = 0; r < 2; r++) {
                int idx = tid + r * 256;
                int krow = idx >> 5, cg = idx & 31;
                uint32_t dst = (uint32_t)__cvta_generic_to_shared(&Bs[nb][krow][cg * 4]);
                cp_async16(dst, W + (size_t)(k0 + krow) * N + n0 + cg * 4);
            }
            cp_async_commit();
        }

        // compute on current buffer: two k8 steps, 3xTF32 each
        #pragma unroll
        for (int kk = 0; kk < 16; kk += 8) {
            uint32_t ah[2][4], al[2][4];
            #pragma unroll
            for (int mi = 0; mi < 2; mi++) {
                int row = wm + mi * 16 + grp;
                float a0 = As[buf][row    ][kk + tig    ];
                float a1 = As[buf][row + 8][kk + tig    ];
                float a2 = As[buf][row    ][kk + tig + 4];
                float a3 = As[buf][row + 8][kk + tig + 4];
                ah[mi][0] = f2tf32(a0); al[mi][0] = f2tf32(a0 - __uint_as_float(ah[mi][0]));
                ah[mi][1] = f2tf32(a1); al[mi][1] = f2tf32(a1 - __uint_as_float(ah[mi][1]));
                ah[mi][2] = f2tf32(a2); al[mi][2] = f2tf32(a2 - __uint_as_float(ah[mi][2]));
                ah[mi][3] = f2tf32(a3); al[mi][3] = f2tf32(a3 - __uint_as_float(ah[mi][3]));
            }
            uint32_t bh[8][2], bl[8][2];
            #pragma unroll
            for (int ni = 0; ni < 8; ni++) {
                int n = wn + ni * 8 + grp;
                float b0 = Bs[buf][kk + tig    ][n];
                float b1 = Bs[buf][kk + tig + 4][n];
                bh[ni][0] = f2tf32(b0); bl[ni][0] = f2tf32(b0 - __uint_as_float(bh[ni][0]));
                bh[ni][1] = f2tf32(b1); bl[ni][1] = f2tf32(b1 - __uint_as_float(bh[ni][1]));
            }
            #pragma unroll
            for (int mi = 0; mi < 2; mi++) {
                #pragma unroll
                for (int ni = 0; ni < 8; ni++) {
                    // low-order terms first, hi*hi last
                    mma_tf32(acc[mi][ni], al[mi][0], al[mi][1], al[mi][2], al[mi][3],
                             bh[ni][0], bh[ni][1]);
                    mma_tf32(acc[mi][ni], ah[mi][0], ah[mi][1], ah[mi][2], ah[mi][3],
                             bl[ni][0], bl[ni][1]);
                    mma_tf32(acc[mi][ni], ah[mi][0], ah[mi][1], ah[mi][2], ah[mi][3],
                             bh[ni][0], bh[ni][1]);
                }
            }
        }
        __syncthreads();
        buf ^= 1;
    }

    // ---- epilogue ----
    #pragma unroll
    for (int mi = 0; mi < 2; mi++) {
        int row0 = m0 + wm + mi * 16 + grp;
        #pragma unroll
        for (int ni = 0; ni < 8; ni++) {
            int col = n0 + wn + ni * 8 + tig * 2;
            float b0 = bias[col], b1 = bias[col + 1];
            float v0 = acc[mi][ni][0] + b0;
            float v1 = acc[mi][ni][1] + b1;
            float v2 = acc[mi][ni][2] + b0;
            float v3 = acc[mi][ni][3] + b1;
            if (act == 1) {
                v0 = 0.5f * v0 * (1.0f + erff(v0 * 0.70710678118654752f));
                v1 = 0.5f * v1 * (1.0f + erff(v1 * 0.70710678118654752f));
                v2 = 0.5f * v2 * (1.0f + erff(v2 * 0.70710678118654752f));
                v3 = 0.5f * v3 * (1.0f + erff(v3 * 0.70710678118654752f));
            }
            *(float2*)(C + (size_t)row0 * N + col)       = make_float2(v0, v1);
            *(float2*)(C + (size_t)(row0 + 8) * N + col) = make_float2(v2, v3);
        }
    }
}

// ---------------- local (banded) attention, flash-style ----------------
__global__ __launch_bounds__(256) void local_attn_kernel(
    const float* __restrict__ Q, const float* __restrict__ K,
    const float* __restrict__ V, const int* __restrict__ amask,
    float* __restrict__ O)
{
    __shared__ float Qs[64][65];
    __shared__ float KVs[64][65];
    const int q0 = blockIdx.x * 64;
    const int hh = blockIdx.y;
    const int b  = blockIdx.z;
    const int tid = threadIdx.x;
    const int tx = tid & 15, ty = tid >> 4;
    const unsigned FULL = 0xffffffffu;

    for (int idx = tid; idx < 64 * 64; idx += 256) {
        int r = idx >> 6, d = idx & 63;
        Qs[r][d] = Q[((size_t)(b * S_ + q0 + r)) * H_ + hh * DH_ + d];
    }

    float m[4], lsum[4], acc[4][4];
    #pragma unroll
    for (int i = 0; i < 4; i++) {
        m[i] = -1e30f; lsum[i] = 0.f;
        #pragma unroll
        for (int j = 0; j < 4; j++) acc[i][j] = 0.f;
    }

    for (int kt = 0; kt < 9; kt++) {
        const int ks = q0 - 256 + kt * 64;
        if (ks + 64 <= 0 || ks >= S_) continue;
        __syncthreads();
        for (int idx = tid; idx < 64 * 64; idx += 256) {
            int c = idx >> 6, d = idx & 63;
            int kg = ks + c;
            KVs[c][d] = (kg >= 0 && kg < S_)
                ? K[((size_t)(b * S_ + kg)) * H_ + hh * DH_ + d] : 0.f;
        }
        __syncthreads();

        float s[4][4];
        #pragma unroll
        for (int i = 0; i < 4; i++)
            #pragma unroll
            for (int j = 0; j < 4; j++) s[i][j] = 0.f;
        #pragma unroll 8
        for (int d = 0; d < 64; d++) {
            float qv[4], kv[4];
            #pragma unroll
            for (int rr = 0; rr < 4; rr++) qv[rr] = Qs[ty * 4 + rr][d];
            #pragma unroll
            for (int cc = 0; cc < 4; cc++) kv[cc] = KVs[tx * 4 + cc][d];
            #pragma unroll
            for (int rr = 0; rr < 4; rr++)
                #pragma unroll
                for (int cc = 0; cc < 4; cc++) s[rr][cc] += qv[rr] * kv[cc];
        }

        float p[4][4];
        #pragma unroll
        for (int rr = 0; rr < 4; rr++) {
            int qg = q0 + ty * 4 + rr;
            float sv[4];
            float tmax = -1e30f;
            #pragma unroll
            for (int cc = 0; cc < 4; cc++) {
                int kg = ks + tx * 4 + cc;
                int delta = kg - qg;
                bool ok = (kg >= 0) && (kg < S_) && (delta >= -WIN_) && (delta <= WIN_)
                          && (amask[b * S_ + kg] > 0);
                sv[cc] = ok ? s[rr][cc] * 0.125f : -1e9f;
                tmax = fmaxf(tmax, sv[cc]);
            }
            #pragma unroll
            for (int o = 8; o; o >>= 1)
                tmax = fmaxf(tmax, __shfl_xor_sync(FULL, tmax, o, 16));
            float mn = fmaxf(m[rr], tmax);
            float scale = __expf(m[rr] - mn);
            float psum = 0.f;
            #pragma unroll
            for (int cc = 0; cc < 4; cc++) {
                p[rr][cc] = __expf(sv[cc] - mn);
                psum += p[rr][cc];
            }
            #pragma unroll
            for (int o = 8; o; o >>= 1)
                psum += __shfl_xor_sync(FULL, psum, o, 16);
            lsum[rr] = lsum[rr] * scale + psum;
            #pragma unroll
            for (int dd = 0; dd < 4; dd++) acc[rr][dd] *= scale;
            m[rr] = mn;
        }

        __syncthreads();
        for (int idx = tid; idx < 64 * 64; idx += 256) {
            int c = idx >> 6, d = idx & 63;
            int kg = ks + c;
            KVs[c][d] = (kg >= 0 && kg < S_)
                ? V[((size_t)(b * S_ + kg)) * H_ + hh * DH_ + d] : 0.f;
        }
        __syncthreads();

        for (int jj = 0; jj < 64; jj += 4) {
            const int src = jj >> 2;
            #pragma unroll
            for (int cc = 0; cc < 4; cc++) {
                const int j = jj + cc;
                float vv0 = KVs[j][tx * 4 + 0];
                float vv1 = KVs[j][tx * 4 + 1];
                float vv2 = KVs[j][tx * 4 + 2];
                float vv3 = KVs[j][tx * 4 + 3];
                #pragma unroll
                for (int rr = 0; rr < 4; rr++) {
                    float pj = __shfl_sync(FULL, p[rr][cc], src, 16);
                    acc[rr][0] += pj * vv0;
                    acc[rr][1] += pj * vv1;
                    acc[rr][2] += pj * vv2;
                    acc[rr][3] += pj * vv3;
                }
            }
        }
    }

    #pragma unroll
    for (int rr = 0; rr < 4; rr++) {
        float inv = 1.f / lsum[rr];
        int qg = q0 + ty * 4 + rr;
        #pragma unroll
        for (int dd = 0; dd < 4; dd++) {
            O[((size_t)(b * S_ + qg)) * H_ + hh * DH_ + tx * 4 + dd] = acc[rr][dd] * inv;
        }
    }
}

// ---------------- pooling head ----------------
__global__ __launch_bounds__(256) void attn_score_kernel(
    const float* __restrict__ h, const float* __restrict__ aw, float* __restrict__ sc)
{
    int t = blockIdx.x;
    int tid = threadIdx.x;
    float acc = 0.f;
    #pragma unroll
    for (int i = 0; i < 3; i++) {
        int c = tid + i * 256;
        acc += h[(size_t)t * H_ + c] * aw[c];
    }
    float s = block_reduce_sum(acc);
    if (tid == 0) sc[t] = s;
}

__global__ __launch_bounds__(256) void softmax_s_kernel(
    const float* __restrict__ sc, float* __restrict__ pr)
{
    int b = blockIdx.x;
    int tid = threadIdx.x;
    float v[4];
    float mx = -1e30f;
    #pragma unroll
    for (int i = 0; i < 4; i++) {
        v[i] = sc[b * S_ + tid + i * 256];
        mx = fmaxf(mx, v[i]);
    }
    mx = block_reduce_max(mx);
    float e[4], ps = 0.f;
    #pragma unroll
    for (int i = 0; i < 4; i++) { e[i] = __expf(v[i] - mx); ps += e[i]; }
    float tot = block_reduce_sum(ps);
    float inv = 1.f / tot;
    #pragma unroll
    for (int i = 0; i < 4; i++) pr[b * S_ + tid + i * 256] = e[i] * inv;
}

__global__ __launch_bounds__(256) void pool_kernel(
    const float* __restrict__ h, const float* __restrict__ pr, float* __restrict__ pooled)
{
    int d = blockIdx.x * 256 + threadIdx.x;
    int b = blockIdx.y;
    float acc = 0.f;
    for (int s = 0; s < S_; s++) {
        acc += h[((size_t)(b * S_ + s)) * H_ + d] * pr[b * S_ + s];
    }
    pooled[b * H_ + d] = acc;
}

__global__ __launch_bounds__(256) void final_kernel(
    const float* __restrict__ pooled, const float* __restrict__ Wc,
    const float* __restrict__ bc, float* __restrict__ out)
{
    int b = blockIdx.x;
    int tid = threadIdx.x;
    float acc = 0.f;
    #pragma unroll
    for (int i = 0; i < 3; i++) {
        int c = tid + i * 256;
        acc += pooled[b * H_ + c] * Wc[c];
    }
    float s = block_reduce_sum(acc);
    if (tid == 0) out[b] = s + bc[0];
}

// ---------------- host launcher ----------------
extern "C" void kernel_launch(void* const* d_in, const int* in_sizes, int n_in,
                              void* d_out, int out_size)
{
    (void)in_sizes; (void)n_in; (void)out_size;
    const float* WE   = (const float*)d_in[0];
    const float* PE   = (const float*)d_in[1];
    const float* Eg   = (const float*)d_in[2];
    const float* Eb   = (const float*)d_in[3];
    const float* Wq   = (const float*)d_in[4];
    const float* bq   = (const float*)d_in[5];
    const float* Wk   = (const float*)d_in[6];
    const float* bk   = (const float*)d_in[7];
    const float* Wv   = (const float*)d_in[8];
    const float* bv   = (const float*)d_in[9];
    const float* Wo   = (const float*)d_in[10];
    const float* bo   = (const float*)d_in[11];
    const float* g1   = (const float*)d_in[12];
    const float* beta1= (const float*)d_in[13];
    const float* W1   = (const float*)d_in[14];
    const float* b1   = (const float*)d_in[15];
    const float* W2   = (const float*)d_in[16];
    const float* b2   = (const float*)d_in[17];
    const float* g2   = (const float*)d_in[18];
    const float* beta2= (const float*)d_in[19];
    const float* aw   = (const float*)d_in[20];
    const float* Wc   = (const float*)d_in[21];
    const float* bc   = (const float*)d_in[22];
    const int*   ids  = (const int*)d_in[23];
    const int*   am   = (const int*)d_in[24];
    float* out = (float*)d_out;

    float *h, *q, *k, *v, *a, *ffn, *sc, *pr, *pooled;
    cudaGetSymbolAddress((void**)&h,   g_h);
    cudaGetSymbolAddress((void**)&q,   g_q);
    cudaGetSymbolAddress((void**)&k,   g_k);
    cudaGetSymbolAddress((void**)&v,   g_v);
    cudaGetSymbolAddress((void**)&a,   g_a);
    cudaGetSymbolAddress((void**)&ffn, g_ffn);
    cudaGetSymbolAddress((void**)&sc,  g_sc);
    cudaGetSymbolAddress((void**)&pr,  g_pr);
    cudaGetSymbolAddress((void**)&pooled, g_pool);

    embed_ln_kernel<<<BS_, 256>>>(WE, PE, Eg, Eb, ids, h);

    dim3 g768(H_ / 128, BS_ / 128);    // (6, 32)
    dim3 g3072(FF_ / 128, BS_ / 128);  // (24, 32)
    dim3 gattn(S_ / 64, NH_, B_);      // (16, 12, 4)

    for (int l = 0; l < L_; l++) {
        const float* Wq_l = Wq + (size_t)l * H_ * H_;
        const float* Wk_l = Wk + (size_t)l * H_ * H_;
        const float* Wv_l = Wv + (size_t)l * H_ * H_;
        const float* Wo_l = Wo + (size_t)l * H_ * H_;
        const float* W1_l = W1 + (size_t)l * H_ * FF_;
        const float* W2_l = W2 + (size_t)l * FF_ * H_;

        tgemm_kernel<<<g768, 256>>>(h, Wq_l, bq + l * H_, q, BS_, H_, H_, 0);
        tgemm_kernel<<<g768, 256>>>(h, Wk_l, bk + l * H_, k, BS_, H_, H_, 0);
        tgemm_kernel<<<g768, 256>>>(h, Wv_l, bv + l * H_, v, BS_, H_, H_, 0);

        local_attn_kernel<<<gattn, 256>>>(q, k, v, am, a);

        tgemm_kernel<<<g768, 256>>>(a, Wo_l, bo + l * H_, q, BS_, H_, H_, 0);
        add_ln_kernel<<<BS_, 256>>>(h, q, g1 + l * H_, beta1 + l * H_);

        tgemm_kernel<<<g3072, 256>>>(h, W1_l, b1 + l * FF_, ffn, BS_, FF_, H_, 1);
        tgemm_kernel<<<g768, 256>>>(ffn, W2_l, b2 + l * H_, q, BS_, H_, FF_, 0);
        add_ln_kernel<<<BS_, 256>>>(h, q, g2 + l * H_, beta2 + l * H_);
    }

    attn_score_kernel<<<BS_, 256>>>(h, aw, sc);
    softmax_s_kernel<<<B_, 256>>>(sc, pr);
    pool_kernel<<<dim3(H_ / 256, B_), 256>>>(h, pr, pooled);
    final_kernel<<<B_, 256>>>(pooled, Wc, bc, out);
}

// round 5
// speedup vs baseline: 2.1271x; 1.6986x over previous
#include <cuda_runtime.h>
#include <cuda_bf16.h>
#include <cstdint>
#include <math.h>

#define L_  12
#define NH_ 12
#define DH_ 64
#define H_  768
#define FF_ 3072
#define S_  1024
#define B_  4
#define BS_ (B_ * S_)   // 4096
#define WIN_ 256
#define QKVS 2304       // fused qkv row stride

typedef __nv_bfloat16 bf16;

// ---------------- scratch (no allocations allowed) ----------------
// pre-transposed, hi/lo-split weights: layout [N][K] bf16
__device__ bf16 g_wqkv_hi[L_ * QKVS * H_];
__device__ bf16 g_wqkv_lo[L_ * QKVS * H_];
__device__ bf16 g_wot_hi [L_ * H_ * H_];
__device__ bf16 g_wot_lo [L_ * H_ * H_];
__device__ bf16 g_w1t_hi [L_ * FF_ * H_];
__device__ bf16 g_w1t_lo [L_ * FF_ * H_];
__device__ bf16 g_w2t_hi [L_ * H_ * FF_];
__device__ bf16 g_w2t_lo [L_ * H_ * FF_];
__device__ float g_bqkv  [L_ * QKVS];

// activations
__device__ float g_h   [BS_ * H_];
__device__ bf16  g_h_hi[BS_ * H_];
__device__ bf16  g_h_lo[BS_ * H_];
__device__ float g_qkv [BS_ * QKVS];
__device__ bf16  g_a_hi[BS_ * H_];
__device__ bf16  g_a_lo[BS_ * H_];
__device__ bf16  g_f_hi[BS_ * FF_];
__device__ bf16  g_f_lo[BS_ * FF_];
__device__ float g_r   [BS_ * H_];
__device__ float g_sc  [BS_];
__device__ float g_pr  [BS_];
__device__ float g_pool[B_ * H_];

__device__ __forceinline__ void split_bf16(float x, bf16& hi, bf16& lo) {
    hi = __float2bfloat16_rn(x);
    lo = __float2bfloat16_rn(x - __bfloat162float(hi));
}

// ---------------- reduction helpers ----------------
__device__ __forceinline__ float block_reduce_sum(float v) {
    __shared__ float red[32];
    int lane = threadIdx.x & 31, wid = threadIdx.x >> 5;
    #pragma unroll
    for (int o = 16; o; o >>= 1) v += __shfl_xor_sync(0xffffffffu, v, o);
    if (lane == 0) red[wid] = v;
    __syncthreads();
    int nw = (blockDim.x + 31) >> 5;
    v = (threadIdx.x < nw) ? red[threadIdx.x] : 0.f;
    if (wid == 0) {
        #pragma unroll
        for (int o = 16; o; o >>= 1) v += __shfl_xor_sync(0xffffffffu, v, o);
    }
    if (threadIdx.x == 0) red[0] = v;
    __syncthreads();
    v = red[0];
    __syncthreads();
    return v;
}

__device__ __forceinline__ float block_reduce_max(float v) {
    __shared__ float red[32];
    int lane = threadIdx.x & 31, wid = threadIdx.x >> 5;
    #pragma unroll
    for (int o = 16; o; o >>= 1) v = fmaxf(v, __shfl_xor_sync(0xffffffffu, v, o));
    if (lane == 0) red[wid] = v;
    __syncthreads();
    int nw = (blockDim.x + 31) >> 5;
    v = (threadIdx.x < nw) ? red[threadIdx.x] : -1e30f;
    if (wid == 0) {
        #pragma unroll
        for (int o = 16; o; o >>= 1) v = fmaxf(v, __shfl_xor_sync(0xffffffffu, v, o));
    }
    if (threadIdx.x == 0) red[0] = v;
    __syncthreads();
    v = red[0];
    __syncthreads();
    return v;
}

// ---------------- weight transpose + hi/lo split ----------------
// src: [K][N] fp32 (row-major n). dst: [N][K] bf16 hi/lo.
__global__ __launch_bounds__(256) void wsplit_kernel(
    const float* __restrict__ src, bf16* __restrict__ dhi, bf16* __restrict__ dlo,
    int K, int N)
{
    __shared__ float t[32][33];
    int tx = threadIdx.x & 31, ty = threadIdx.x >> 5;   // 32 x 8
    int n0 = blockIdx.x * 32, k0 = blockIdx.y * 32;
    #pragma unroll
    for (int i = 0; i < 4; i++)
        t[ty + i * 8][tx] = src[(size_t)(k0 + ty + i * 8) * N + n0 + tx];
    __syncthreads();
    #pragma unroll
    for (int i = 0; i < 4; i++) {
        int r = ty + i * 8;
        float x = t[tx][r];
        bf16 hi, lo; split_bf16(x, hi, lo);
        size_t o = (size_t)(n0 + r) * K + k0 + tx;
        dhi[o] = hi; dlo[o] = lo;
    }
}

__global__ __launch_bounds__(256) void bias_concat_kernel(
    const float* __restrict__ bq, const float* __restrict__ bk,
    const float* __restrict__ bv, float* __restrict__ bqkv)
{
    int l = blockIdx.x;
    for (int n = threadIdx.x; n < QKVS; n += 256) {
        float v;
        if (n < H_)            v = bq[l * H_ + n];
        else if (n < 2 * H_)   v = bk[l * H_ + n - H_];
        else                   v = bv[l * H_ + n - 2 * H_];
        bqkv[l * QKVS + n] = v;
    }
}

// ---------------- embedding + LN ----------------
__global__ __launch_bounds__(256) void embed_ln_kernel(
    const float* __restrict__ WE, const float* __restrict__ PE,
    const float* __restrict__ g, const float* __restrict__ be,
    const int* __restrict__ ids,
    float* __restrict__ out, bf16* __restrict__ ohi, bf16* __restrict__ olo)
{
    int t = blockIdx.x;
    int s = t & (S_ - 1);
    int tid = threadIdx.x;
    int id = ids[t];
    float v[3];
    #pragma unroll
    for (int i = 0; i < 3; i++) {
        int c = tid + i * 256;
        v[i] = WE[(size_t)id * H_ + c] + PE[(size_t)s * H_ + c];
    }
    float ssum = block_reduce_sum(v[0] + v[1] + v[2]);
    float m = ssum * (1.f / H_);
    float sq = 0.f;
    #pragma unroll
    for (int i = 0; i < 3; i++) { float d = v[i] - m; sq += d * d; }
    float vs = block_reduce_sum(sq);
    float rs = rsqrtf(vs * (1.f / H_) + 1e-5f);
    #pragma unroll
    for (int i = 0; i < 3; i++) {
        int c = tid + i * 256;
        float y = (v[i] - m) * rs * g[c] + be[c];
        size_t o = (size_t)t * H_ + c;
        out[o] = y;
        bf16 hi, lo; split_bf16(y, hi, lo);
        ohi[o] = hi; olo[o] = lo;
    }
}

// ---------------- residual add + LN (in-place on h) ----------------
__global__ __launch_bounds__(256) void add_ln_kernel(
    float* __restrict__ h, const float* __restrict__ r,
    const float* __restrict__ g, const float* __restrict__ be,
    bf16* __restrict__ ohi, bf16* __restrict__ olo)
{
    int t = blockIdx.x;
    int tid = threadIdx.x;
    float v[3];
    #pragma unroll
    for (int i = 0; i < 3; i++) {
        int c = tid + i * 256;
        v[i] = h[(size_t)t * H_ + c] + r[(size_t)t * H_ + c];
    }
    float ssum = block_reduce_sum(v[0] + v[1] + v[2]);
    float m = ssum * (1.f / H_);
    float sq = 0.f;
    #pragma unroll
    for (int i = 0; i < 3; i++) { float d = v[i] - m; sq += d * d; }
    float vs = block_reduce_sum(sq);
    float rs = rsqrtf(vs * (1.f / H_) + 1e-5f);
    #pragma unroll
    for (int i = 0; i < 3; i++) {
        int c = tid + i * 256;
        float y = (v[i] - m) * rs * g[c] + be[c];
        size_t o = (size_t)t * H_ + c;
        h[o] = y;
        bf16 hi, lo; split_bf16(y, hi, lo);
        ohi[o] = hi; olo[o] = lo;
    }
}

// ================= bf16x3 tensor-core GEMM =================
// C[M,N] = A[M,K] @ B^T (B pre-transposed [N][K]) + bias.
// A,B given as hi/lo bf16. 128x128 tile, BK=32, 8 warps (4x2), warp 32x64.
// mode 0: fp32 out. mode 1: GELU -> bf16 hi/lo out.

#define PSTR 20                 // packed row stride (16 packs + 4 pad)
#define STG  (128 * PSTR)       // uint32 per tile stage

__device__ __forceinline__ void cp_async16(uint32_t smem_addr, const void* gptr) {
    asm volatile("cp.async.cg.shared.global [%0], [%1], 16;\n"
                 :: "r"(smem_addr), "l"(gptr));
}
__device__ __forceinline__ void cp_async_commit() {
    asm volatile("cp.async.commit_group;\n");
}
__device__ __forceinline__ void cp_async_wait0() {
    asm volatile("cp.async.wait_group 0;\n");
}
__device__ __forceinline__ void mma_bf16(
    float* acc, uint32_t a0, uint32_t a1, uint32_t a2, uint32_t a3,
    uint32_t b0, uint32_t b1)
{
    asm volatile(
        "mma.sync.aligned.m16n8k16.row.col.f32.bf16.bf16.f32 "
        "{%0,%1,%2,%3}, {%4,%5,%6,%7}, {%8,%9}, {%0,%1,%2,%3};\n"
        : "+f"(acc[0]), "+f"(acc[1]), "+f"(acc[2]), "+f"(acc[3])
        : "r"(a0), "r"(a1), "r"(a2), "r"(a3), "r"(b0), "r"(b1));
}

__global__ __launch_bounds__(256) void tgemm_kernel(
    const bf16* __restrict__ Ah, const bf16* __restrict__ Al,
    const bf16* __restrict__ Bh, const bf16* __restrict__ Bl,
    const float* __restrict__ bias,
    float* __restrict__ Cf, bf16* __restrict__ Ch, bf16* __restrict__ Cl,
    int M, int N, int K, int mode)
{
    extern __shared__ uint32_t smem_u[];
    uint32_t* AsH = smem_u;                 // [2][128][PSTR]
    uint32_t* AsL = smem_u + 2 * STG;
    uint32_t* BsH = smem_u + 4 * STG;
    uint32_t* BsL = smem_u + 6 * STG;

    const int tid  = threadIdx.x;
    const int warp = tid >> 5;
    const int lane = tid & 31;
    const int m0 = blockIdx.y * 128;
    const int n0 = blockIdx.x * 128;
    const int wm = (warp >> 1) * 32;
    const int wn = (warp & 1) * 64;
    const int grp = lane >> 2;
    const int tig = lane & 3;

    const int lrow = tid >> 2;        // loader row (0..63) -> two rows per thread pass
    const int lc   = tid & 3;         // 16B chunk 0..3

    float acc[2][8][4];
    #pragma unroll
    for (int mi = 0; mi < 2; mi++)
        #pragma unroll
        for (int ni = 0; ni < 8; ni++)
            #pragma unroll
            for (int c = 0; c < 4; c++) acc[mi][ni][c] = 0.f;

    const int KT = K >> 5;     // BK = 32

    // loader lambda-ish: stage s (0/1), k0
    #define LOAD_STAGE(s, k0)                                                          \
    {                                                                                  \
        _Pragma("unroll")                                                              \
        for (int r = 0; r < 2; r++) {                                                  \
            int idx = tid + r * 256;                                                   \
            int row = idx >> 2, c = idx & 3;                                           \
            uint32_t doff = ((s) * STG + row * PSTR + c * 4) * 4;                      \
            uint32_t base = (uint32_t)__cvta_generic_to_shared(smem_u);                \
            size_t aoff = (size_t)(m0 + row) * K + (k0) + c * 8;                       \
            size_t boff = (size_t)(n0 + row) * K + (k0) + c * 8;                       \
            cp_async16(base + (0 * 2 * STG) * 4 + doff, Ah + aoff);                    \
            cp_async16(base + (1 * 2 * STG) * 4 + doff, Al + aoff);                    \
            cp_async16(base + (2 * 2 * STG) * 4 + doff, Bh + boff);                    \
            cp_async16(base + (3 * 2 * STG) * 4 + doff, Bl + boff);                    \
        }                                                                              \
        cp_async_commit();                                                             \
    }

    LOAD_STAGE(0, 0)

    int buf = 0;
    for (int kt = 0; kt < KT; kt++) {
        cp_async_wait0();
        __syncthreads();
        if (kt + 1 < KT) {
            LOAD_STAGE(buf ^ 1, (kt + 1) << 5)
        }

        const uint32_t* aH = AsH + buf * STG;
        const uint32_t* aL = AsL + buf * STG;
        const uint32_t* bH = BsH + buf * STG;
        const uint32_t* bL = BsL + buf * STG;

        #pragma unroll
        for (int st = 0; st < 2; st++) {     // two k16 steps, pack base p0
            const int p0 = st * 8;
            uint32_t ah[2][4], al[2][4];
            #pragma unroll
            for (int mi = 0; mi < 2; mi++) {
                int r0 = (wm + mi * 16 + grp) * PSTR;
                int r1 = r0 + 8 * PSTR;
                ah[mi][0] = aH[r0 + p0 + tig];
                ah[mi][1] = aH[r1 + p0 + tig];
                ah[mi][2] = aH[r0 + p0 + 4 + tig];
                ah[mi][3] = aH[r1 + p0 + 4 + tig];
                al[mi][0] = aL[r0 + p0 + tig];
                al[mi][1] = aL[r1 + p0 + tig];
                al[mi][2] = aL[r0 + p0 + 4 + tig];
                al[mi][3] = aL[r1 + p0 + 4 + tig];
            }
            uint32_t bh[8][2], bl[8][2];
            #pragma unroll
            for (int ni = 0; ni < 8; ni++) {
                int rn = (wn + ni * 8 + grp) * PSTR;
                bh[ni][0] = bH[rn + p0 + tig];
                bh[ni][1] = bH[rn + p0 + 4 + tig];
                bl[ni][0] = bL[rn + p0 + tig];
                bl[ni][1] = bL[rn + p0 + 4 + tig];
            }
            #pragma unroll
            for (int mi = 0; mi < 2; mi++) {
                #pragma unroll
                for (int ni = 0; ni < 8; ni++) {
                    mma_bf16(acc[mi][ni], al[mi][0], al[mi][1], al[mi][2], al[mi][3],
                             bh[ni][0], bh[ni][1]);
                    mma_bf16(acc[mi][ni], ah[mi][0], ah[mi][1], ah[mi][2], ah[mi][3],
                             bl[ni][0], bl[ni][1]);
                    mma_bf16(acc[mi][ni], ah[mi][0], ah[mi][1], ah[mi][2], ah[mi][3],
                             bh[ni][0], bh[ni][1]);
                }
            }
        }
        __syncthreads();
        buf ^= 1;
    }

    // ---- epilogue ----
    #pragma unroll
    for (int mi = 0; mi < 2; mi++) {
        int row0 = m0 + wm + mi * 16 + grp;
        #pragma unroll
        for (int ni = 0; ni < 8; ni++) {
            int col = n0 + wn + ni * 8 + tig * 2;
            float b0 = bias[col], b1 = bias[col + 1];
            float v0 = acc[mi][ni][0] + b0;
            float v1 = acc[mi][ni][1] + b1;
            float v2 = acc[mi][ni][2] + b0;
            float v3 = acc[mi][ni][3] + b1;
            if (mode == 1) {
                v0 = 0.5f * v0 * (1.0f + erff(v0 * 0.70710678118654752f));
                v1 = 0.5f * v1 * (1.0f + erff(v1 * 0.70710678118654752f));
                v2 = 0.5f * v2 * (1.0f + erff(v2 * 0.70710678118654752f));
                v3 = 0.5f * v3 * (1.0f + erff(v3 * 0.70710678118654752f));
                size_t o0 = (size_t)row0 * N + col;
                size_t o1 = (size_t)(row0 + 8) * N + col;
                bf16 hi, lo;
                split_bf16(v0, hi, lo); Ch[o0]     = hi; Cl[o0]     = lo;
                split_bf16(v1, hi, lo); Ch[o0 + 1] = hi; Cl[o0 + 1] = lo;
                split_bf16(v2, hi, lo); Ch[o1]     = hi; Cl[o1]     = lo;
                split_bf16(v3, hi, lo); Ch[o1 + 1] = hi; Cl[o1 + 1] = lo;
            } else {
                *(float2*)(Cf + (size_t)row0 * N + col)       = make_float2(v0, v1);
                *(float2*)(Cf + (size_t)(row0 + 8) * N + col) = make_float2(v2, v3);
            }
        }
    }
}

// ---------------- local (banded) attention, flash-style ----------------
// reads fused qkv buffer (stride QKVS), writes hi/lo bf16 attention output
__global__ __launch_bounds__(256) void local_attn_kernel(
    const float* __restrict__ QKV, const int* __restrict__ amask,
    bf16* __restrict__ Ohi, bf16* __restrict__ Olo)
{
    __shared__ float Qs[64][65];
    __shared__ float KVs[64][65];
    const int q0 = blockIdx.x * 64;
    const int hh = blockIdx.y;
    const int b  = blockIdx.z;
    const int tid = threadIdx.x;
    const int tx = tid & 15, ty = tid >> 4;
    const unsigned FULL = 0xffffffffu;

    for (int idx = tid; idx < 64 * 64; idx += 256) {
        int r = idx >> 6, d = idx & 63;
        Qs[r][d] = QKV[((size_t)(b * S_ + q0 + r)) * QKVS + hh * DH_ + d];
    }

    float m[4], lsum[4], acc[4][4];
    #pragma unroll
    for (int i = 0; i < 4; i++) {
        m[i] = -1e30f; lsum[i] = 0.f;
        #pragma unroll
        for (int j = 0; j < 4; j++) acc[i][j] = 0.f;
    }

    for (int kt = 0; kt < 9; kt++) {
        const int ks = q0 - 256 + kt * 64;
        if (ks + 64 <= 0 || ks >= S_) continue;
        __syncthreads();
        for (int idx = tid; idx < 64 * 64; idx += 256) {
            int c = idx >> 6, d = idx & 63;
            int kg = ks + c;
            KVs[c][d] = (kg >= 0 && kg < S_)
                ? QKV[((size_t)(b * S_ + kg)) * QKVS + H_ + hh * DH_ + d] : 0.f;
        }
        __syncthreads();

        float s[4][4];
        #pragma unroll
        for (int i = 0; i < 4; i++)
            #pragma unroll
            for (int j = 0; j < 4; j++) s[i][j] = 0.f;
        #pragma unroll 8
        for (int d = 0; d < 64; d++) {
            float qv[4], kv[4];
            #pragma unroll
            for (int rr = 0; rr < 4; rr++) qv[rr] = Qs[ty * 4 + rr][d];
            #pragma unroll
            for (int cc = 0; cc < 4; cc++) kv[cc] = KVs[tx * 4 + cc][d];
            #pragma unroll
            for (int rr = 0; rr < 4; rr++)
                #pragma unroll
                for (int cc = 0; cc < 4; cc++) s[rr][cc] += qv[rr] * kv[cc];
        }

        float p[4][4];
        #pragma unroll
        for (int rr = 0; rr < 4; rr++) {
            int qg = q0 + ty * 4 + rr;
            float sv[4];
            float tmax = -1e30f;
            #pragma unroll
            for (int cc = 0; cc < 4; cc++) {
                int kg = ks + tx * 4 + cc;
                int delta = kg - qg;
                bool ok = (kg >= 0) && (kg < S_) && (delta >= -WIN_) && (delta <= WIN_)
                          && (amask[b * S_ + kg] > 0);
                sv[cc] = ok ? s[rr][cc] * 0.125f : -1e9f;
                tmax = fmaxf(tmax, sv[cc]);
            }
            #pragma unroll
            for (int o = 8; o; o >>= 1)
                tmax = fmaxf(tmax, __shfl_xor_sync(FULL, tmax, o, 16));
            float mn = fmaxf(m[rr], tmax);
            float scale = __expf(m[rr] - mn);
            float psum = 0.f;
            #pragma unroll
            for (int cc = 0; cc < 4; cc++) {
                p[rr][cc] = __expf(sv[cc] - mn);
                psum += p[rr][cc];
            }
            #pragma unroll
            for (int o = 8; o; o >>= 1)
                psum += __shfl_xor_sync(FULL, psum, o, 16);
            lsum[rr] = lsum[rr] * scale + psum;
            #pragma unroll
            for (int dd = 0; dd < 4; dd++) acc[rr][dd] *= scale;
            m[rr] = mn;
        }

        __syncthreads();
        for (int idx = tid; idx < 64 * 64; idx += 256) {
            int c = idx >> 6, d = idx & 63;
            int kg = ks + c;
            KVs[c][d] = (kg >= 0 && kg < S_)
                ? QKV[((size_t)(b * S_ + kg)) * QKVS + 2 * H_ + hh * DH_ + d] : 0.f;
        }
        __syncthreads();

        for (int jj = 0; jj < 64; jj += 4) {
            const int src = jj >> 2;
            #pragma unroll
            for (int cc = 0; cc < 4; cc++) {
                const int j = jj + cc;
                float vv0 = KVs[j][tx * 4 + 0];
                float vv1 = KVs[j][tx * 4 + 1];
                float vv2 = KVs[j][tx * 4 + 2];
                float vv3 = KVs[j][tx * 4 + 3];
                #pragma unroll
                for (int rr = 0; rr < 4; rr++) {
                    float pj = __shfl_sync(FULL, p[rr][cc], src, 16);
                    acc[rr][0] += pj * vv0;
                    acc[rr][1] += pj * vv1;
                    acc[rr][2] += pj * vv2;
                    acc[rr][3] += pj * vv3;
                }
            }
        }
    }

    #pragma unroll
    for (int rr = 0; rr < 4; rr++) {
        float inv = 1.f / lsum[rr];
        int qg = q0 + ty * 4 + rr;
        #pragma unroll
        for (int dd = 0; dd < 4; dd++) {
            float y = acc[rr][dd] * inv;
            size_t o = ((size_t)(b * S_ + qg)) * H_ + hh * DH_ + tx * 4 + dd;
            bf16 hi, lo; split_bf16(y, hi, lo);
            Ohi[o] = hi; Olo[o] = lo;
        }
    }
}

// ---------------- pooling head ----------------
__global__ __launch_bounds__(256) void attn_score_kernel(
    const float* __restrict__ h, const float* __restrict__ aw, float* __restrict__ sc)
{
    int t = blockIdx.x;
    int tid = threadIdx.x;
    float acc = 0.f;
    #pragma unroll
    for (int i = 0; i < 3; i++) {
        int c = tid + i * 256;
        acc += h[(size_t)t * H_ + c] * aw[c];
    }
    float s = block_reduce_sum(acc);
    if (tid == 0) sc[t] = s;
}

__global__ __launch_bounds__(256) void softmax_s_kernel(
    const float* __restrict__ sc, float* __restrict__ pr)
{
    int b = blockIdx.x;
    int tid = threadIdx.x;
    float v[4];
    float mx = -1e30f;
    #pragma unroll
    for (int i = 0; i < 4; i++) {
        v[i] = sc[b * S_ + tid + i * 256];
        mx = fmaxf(mx, v[i]);
    }
    mx = block_reduce_max(mx);
    float e[4], ps = 0.f;
    #pragma unroll
    for (int i = 0; i < 4; i++) { e[i] = __expf(v[i] - mx); ps += e[i]; }
    float tot = block_reduce_sum(ps);
    float inv = 1.f / tot;
    #pragma unroll
    for (int i = 0; i < 4; i++) pr[b * S_ + tid + i * 256] = e[i] * inv;
}

__global__ __launch_bounds__(256) void pool_kernel(
    const float* __restrict__ h, const float* __restrict__ pr, float* __restrict__ pooled)
{
    int d = blockIdx.x * 256 + threadIdx.x;
    int b = blockIdx.y;
    float acc = 0.f;
    for (int s = 0; s < S_; s++) {
        acc += h[((size_t)(b * S_ + s)) * H_ + d] * pr[b * S_ + s];
    }
    pooled[b * H_ + d] = acc;
}

__global__ __launch_bounds__(256) void final_kernel(
    const float* __restrict__ pooled, const float* __restrict__ Wc,
    const float* __restrict__ bc, float* __restrict__ out)
{
    int b = blockIdx.x;
    int tid = threadIdx.x;
    float acc = 0.f;
    #pragma unroll
    for (int i = 0; i < 3; i++) {
        int c = tid + i * 256;
        acc += pooled[b * H_ + c] * Wc[c];
    }
    float s = block_reduce_sum(acc);
    if (tid == 0) out[b] = s + bc[0];
}

// ---------------- host launcher ----------------
extern "C" void kernel_launch(void* const* d_in, const int* in_sizes, int n_in,
                              void* d_out, int out_size)
{
    (void)in_sizes; (void)n_in; (void)out_size;
    const float* WE   = (const float*)d_in[0];
    const float* PE   = (const float*)d_in[1];
    const float* Eg   = (const float*)d_in[2];
    const float* Eb   = (const float*)d_in[3];
    const float* Wq   = (const float*)d_in[4];
    const float* bq   = (const float*)d_in[5];
    const float* Wk   = (const float*)d_in[6];
    const float* bk   = (const float*)d_in[7];
    const float* Wv   = (const float*)d_in[8];
    const float* bv   = (const float*)d_in[9];
    const float* Wo   = (const float*)d_in[10];
    const float* bo   = (const float*)d_in[11];
    const float* g1   = (const float*)d_in[12];
    const float* beta1= (const float*)d_in[13];
    const float* W1   = (const float*)d_in[14];
    const float* b1   = (const float*)d_in[15];
    const float* W2   = (const float*)d_in[16];
    const float* b2   = (const float*)d_in[17];
    const float* g2   = (const float*)d_in[18];
    const float* beta2= (const float*)d_in[19];
    const float* aw   = (const float*)d_in[20];
    const float* Wc   = (const float*)d_in[21];
    const float* bc   = (const float*)d_in[22];
    const int*   ids  = (const int*)d_in[23];
    const int*   am   = (const int*)d_in[24];
    float* out = (float*)d_out;

    bf16 *wqkv_hi, *wqkv_lo, *wot_hi, *wot_lo, *w1t_hi, *w1t_lo, *w2t_hi, *w2t_lo;
    bf16 *h_hi, *h_lo, *a_hi, *a_lo, *f_hi, *f_lo;
    float *bqkv, *h, *qkv, *r, *sc, *pr, *pooled;
    cudaGetSymbolAddress((void**)&wqkv_hi, g_wqkv_hi);
    cudaGetSymbolAddress((void**)&wqkv_lo, g_wqkv_lo);
    cudaGetSymbolAddress((void**)&wot_hi,  g_wot_hi);
    cudaGetSymbolAddress((void**)&wot_lo,  g_wot_lo);
    cudaGetSymbolAddress((void**)&w1t_hi,  g_w1t_hi);
    cudaGetSymbolAddress((void**)&w1t_lo,  g_w1t_lo);
    cudaGetSymbolAddress((void**)&w2t_hi,  g_w2t_hi);
    cudaGetSymbolAddress((void**)&w2t_lo,  g_w2t_lo);
    cudaGetSymbolAddress((void**)&bqkv,    g_bqkv);
    cudaGetSymbolAddress((void**)&h,       g_h);
    cudaGetSymbolAddress((void**)&h_hi,    g_h_hi);
    cudaGetSymbolAddress((void**)&h_lo,    g_h_lo);
    cudaGetSymbolAddress((void**)&qkv,     g_qkv);
    cudaGetSymbolAddress((void**)&a_hi,    g_a_hi);
    cudaGetSymbolAddress((void**)&a_lo,    g_a_lo);
    cudaGetSymbolAddress((void**)&f_hi,    g_f_hi);
    cudaGetSymbolAddress((void**)&f_lo,    g_f_lo);
    cudaGetSymbolAddress((void**)&r,       g_r);
    cudaGetSymbolAddress((void**)&sc,      g_sc);
    cudaGetSymbolAddress((void**)&pr,      g_pr);
    cudaGetSymbolAddress((void**)&pooled,  g_pool);

    cudaFuncSetAttribute(tgemm_kernel,
                         cudaFuncAttributeMaxDynamicSharedMemorySize, 8 * STG * 4);

    // ---- weight pre-pass: transpose + split ----
    dim3 wb(256);
    dim3 gHH(H_ / 32, H_ / 32);        // 768x768
    dim3 gHF(FF_ / 32, H_ / 32);       // src [768][3072]
    dim3 gFH(H_ / 32, FF_ / 32);       // src [3072][768]
    for (int l = 0; l < L_; l++) {
        wsplit_kernel<<<gHH, wb>>>(Wq + (size_t)l * H_ * H_,
            wqkv_hi + (size_t)l * QKVS * H_,
            wqkv_lo + (size_t)l * QKVS * H_, H_, H_);
        wsplit_kernel<<<gHH, wb>>>(Wk + (size_t)l * H_ * H_,
            wqkv_hi + (size_t)l * QKVS * H_ + (size_t)H_ * H_,
            wqkv_lo + (size_t)l * QKVS * H_ + (size_t)H_ * H_, H_, H_);
        wsplit_kernel<<<gHH, wb>>>(Wv + (size_t)l * H_ * H_,
            wqkv_hi + (size_t)l * QKVS * H_ + (size_t)2 * H_ * H_,
            wqkv_lo + (size_t)l * QKVS * H_ + (size_t)2 * H_ * H_, H_, H_);
        wsplit_kernel<<<gHH, wb>>>(Wo + (size_t)l * H_ * H_,
            wot_hi + (size_t)l * H_ * H_, wot_lo + (size_t)l * H_ * H_, H_, H_);
        wsplit_kernel<<<gHF, wb>>>(W1 + (size_t)l * H_ * FF_,
            w1t_hi + (size_t)l * FF_ * H_, w1t_lo + (size_t)l * FF_ * H_, H_, FF_);
        wsplit_kernel<<<gFH, wb>>>(W2 + (size_t)l * FF_ * H_,
            w2t_hi + (size_t)l * H_ * FF_, w2t_lo + (size_t)l * H_ * FF_, FF_, H_);
    }
    bias_concat_kernel<<<L_, 256>>>(bq, bk, bv, bqkv);

    embed_ln_kernel<<<BS_, 256>>>(WE, PE, Eg, Eb, ids, h, h_hi, h_lo);

    const size_t SMEMB = 8 * STG * 4;
    dim3 gQKV(QKVS / 128, BS_ / 128);   // (18, 32)
    dim3 gO(H_ / 128, BS_ / 128);       // (6, 32)
    dim3 gW1(FF_ / 128, BS_ / 128);     // (24, 32)
    dim3 gattn(S_ / 64, NH_, B_);

    for (int l = 0; l < L_; l++) {
        tgemm_kernel<<<gQKV, 256, SMEMB>>>(h_hi, h_lo,
            wqkv_hi + (size_t)l * QKVS * H_, wqkv_lo + (size_t)l * QKVS * H_,
            bqkv + l * QKVS, qkv, nullptr, nullptr, BS_, QKVS, H_, 0);

        local_attn_kernel<<<gattn, 256>>>(qkv, am, a_hi, a_lo);

        tgemm_kernel<<<gO, 256, SMEMB>>>(a_hi, a_lo,
            wot_hi + (size_t)l * H_ * H_, wot_lo + (size_t)l * H_ * H_,
            bo + l * H_, r, nullptr, nullptr, BS_, H_, H_, 0);
        add_ln_kernel<<<BS_, 256>>>(h, r, g1 + l * H_, beta1 + l * H_, h_hi, h_lo);

        tgemm_kernel<<<gW1, 256, SMEMB>>>(h_hi, h_lo,
            w1t_hi + (size_t)l * FF_ * H_, w1t_lo + (size_t)l * FF_ * H_,
            b1 + l * FF_, nullptr, f_hi, f_lo, BS_, FF_, H_, 1);

        tgemm_kernel<<<gO, 256, SMEMB>>>(f_hi, f_lo,
            w2t_hi + (size_t)l * H_ * FF_, w2t_lo + (size_t)l * H_ * FF_,
            b2 + l * H_, r, nullptr, nullptr, BS_, H_, FF_, 0);
        add_ln_kernel<<<BS_, 256>>>(h, r, g2 + l * H_, beta2 + l * H_, h_hi, h_lo);
    }

    attn_score_kernel<<<BS_, 256>>>(h, aw, sc);
    softmax_s_kernel<<<B_, 256>>>(sc, pr);
    pool_kernel<<<dim3(H_ / 256, B_), 256>>>(h, pr, pooled);
    final_kernel<<<B_, 256>>>(pooled, Wc, bc, out);
}

// round 6
// speedup vs baseline: 2.6984x; 1.2686x over previous
#include <cuda_runtime.h>
#include <cuda_bf16.h>
#include <cstdint>
#include <math.h>

#define L_  12
#define NH_ 12
#define DH_ 64
#define H_  768
#define FF_ 3072
#define S_  1024
#define B_  4
#define BS_ (B_ * S_)   // 4096
#define WIN_ 256
#define QKVS 2304       // fused qkv row stride

typedef __nv_bfloat16 bf16;

// ---------------- scratch (no allocations allowed) ----------------
__device__ bf16 g_wqkv_hi[L_ * QKVS * H_];
__device__ bf16 g_wqkv_lo[L_ * QKVS * H_];
__device__ bf16 g_wot_hi [L_ * H_ * H_];
__device__ bf16 g_wot_lo [L_ * H_ * H_];
__device__ bf16 g_w1t_hi [L_ * FF_ * H_];
__device__ bf16 g_w1t_lo [L_ * FF_ * H_];
__device__ bf16 g_w2t_hi [L_ * H_ * FF_];
__device__ bf16 g_w2t_lo [L_ * H_ * FF_];
__device__ float g_bqkv  [L_ * QKVS];

__device__ float g_h   [BS_ * H_];
__device__ bf16  g_h_hi[BS_ * H_];
__device__ bf16  g_h_lo[BS_ * H_];
__device__ float g_qkv [BS_ * QKVS];
__device__ bf16  g_a_hi[BS_ * H_];
__device__ bf16  g_a_lo[BS_ * H_];
__device__ bf16  g_f_hi[BS_ * FF_];
__device__ bf16  g_f_lo[BS_ * FF_];
__device__ float g_r   [BS_ * H_];
__device__ float g_sc  [BS_];
__device__ float g_pr  [BS_];
__device__ float g_pool[B_ * H_];

__device__ __forceinline__ void split_bf16(float x, bf16& hi, bf16& lo) {
    hi = __float2bfloat16_rn(x);
    lo = __float2bfloat16_rn(x - __bfloat162float(hi));
}

// ---------------- low-level helpers ----------------
__device__ __forceinline__ void cp_async16(uint32_t smem_addr, const void* gptr) {
    asm volatile("cp.async.cg.shared.global [%0], [%1], 16;\n"
                 :: "r"(smem_addr), "l"(gptr));
}
__device__ __forceinline__ void cp_async_commit() {
    asm volatile("cp.async.commit_group;\n");
}
__device__ __forceinline__ void cp_async_wait0() {
    asm volatile("cp.async.wait_group 0;\n");
}
__device__ __forceinline__ void ldsm_x4(uint32_t& r0, uint32_t& r1, uint32_t& r2,
                                        uint32_t& r3, uint32_t a) {
    asm volatile("ldmatrix.sync.aligned.m8n8.x4.shared.b16 {%0,%1,%2,%3}, [%4];"
                 : "=r"(r0), "=r"(r1), "=r"(r2), "=r"(r3) : "r"(a));
}
__device__ __forceinline__ void ldsm_x4_t(uint32_t& r0, uint32_t& r1, uint32_t& r2,
                                          uint32_t& r3, uint32_t a) {
    asm volatile("ldmatrix.sync.aligned.m8n8.x4.trans.shared.b16 {%0,%1,%2,%3}, [%4];"
                 : "=r"(r0), "=r"(r1), "=r"(r2), "=r"(r3) : "r"(a));
}
__device__ __forceinline__ void mma_bf16(
    float* acc, uint32_t a0, uint32_t a1, uint32_t a2, uint32_t a3,
    uint32_t b0, uint32_t b1)
{
    asm volatile(
        "mma.sync.aligned.m16n8k16.row.col.f32.bf16.bf16.f32 "
        "{%0,%1,%2,%3}, {%4,%5,%6,%7}, {%8,%9}, {%0,%1,%2,%3};\n"
        : "+f"(acc[0]), "+f"(acc[1]), "+f"(acc[2]), "+f"(acc[3])
        : "r"(a0), "r"(a1), "r"(a2), "r"(a3), "r"(b0), "r"(b1));
}
__device__ __forceinline__ void packsplit(float a, float b, uint32_t& ph, uint32_t& pl) {
    bf16 ah = __float2bfloat16_rn(a), bh = __float2bfloat16_rn(b);
    float al = a - __bfloat162float(ah), bl = b - __bfloat162float(bh);
    ph = ((uint32_t)__bfloat16_as_ushort(bh) << 16) | (uint32_t)__bfloat16_as_ushort(ah);
    pl = ((uint32_t)__bfloat16_as_ushort(__float2bfloat16_rn(bl)) << 16)
       |  (uint32_t)__bfloat16_as_ushort(__float2bfloat16_rn(al));
}

// ---------------- reduction helpers ----------------
__device__ __forceinline__ float block_reduce_sum(float v) {
    __shared__ float red[32];
    int lane = threadIdx.x & 31, wid = threadIdx.x >> 5;
    #pragma unroll
    for (int o = 16; o; o >>= 1) v += __shfl_xor_sync(0xffffffffu, v, o);
    if (lane == 0) red[wid] = v;
    __syncthreads();
    int nw = (blockDim.x + 31) >> 5;
    v = (threadIdx.x < nw) ? red[threadIdx.x] : 0.f;
    if (wid == 0) {
        #pragma unroll
        for (int o = 16; o; o >>= 1) v += __shfl_xor_sync(0xffffffffu, v, o);
    }
    if (threadIdx.x == 0) red[0] = v;
    __syncthreads();
    v = red[0];
    __syncthreads();
    return v;
}

__device__ __forceinline__ float block_reduce_max(float v) {
    __shared__ float red[32];
    int lane = threadIdx.x & 31, wid = threadIdx.x >> 5;
    #pragma unroll
    for (int o = 16; o; o >>= 1) v = fmaxf(v, __shfl_xor_sync(0xffffffffu, v, o));
    if (lane == 0) red[wid] = v;
    __syncthreads();
    int nw = (blockDim.x + 31) >> 5;
    v = (threadIdx.x < nw) ? red[threadIdx.x] : -1e30f;
    if (wid == 0) {
        #pragma unroll
        for (int o = 16; o; o >>= 1) v = fmaxf(v, __shfl_xor_sync(0xffffffffu, v, o));
    }
    if (threadIdx.x == 0) red[0] = v;
    __syncthreads();
    v = red[0];
    __syncthreads();
    return v;
}

// ---------------- weight transpose + hi/lo split (batched over layers) ----
__global__ __launch_bounds__(256) void wsplit_kernel(
    const float* __restrict__ src, bf16* __restrict__ dhi, bf16* __restrict__ dlo,
    int K, int N, size_t srcStride, size_t dstStride)
{
    __shared__ float t[32][33];
    int l = blockIdx.z;
    src += (size_t)l * srcStride;
    dhi += (size_t)l * dstStride;
    dlo += (size_t)l * dstStride;
    int tx = threadIdx.x & 31, ty = threadIdx.x >> 5;
    int n0 = blockIdx.x * 32, k0 = blockIdx.y * 32;
    #pragma unroll
    for (int i = 0; i < 4; i++)
        t[ty + i * 8][tx] = src[(size_t)(k0 + ty + i * 8) * N + n0 + tx];
    __syncthreads();
    #pragma unroll
    for (int i = 0; i < 4; i++) {
        int r = ty + i * 8;
        float x = t[tx][r];
        bf16 hi, lo; split_bf16(x, hi, lo);
        size_t o = (size_t)(n0 + r) * K + k0 + tx;
        dhi[o] = hi; dlo[o] = lo;
    }
}

__global__ __launch_bounds__(256) void bias_concat_kernel(
    const float* __restrict__ bq, const float* __restrict__ bk,
    const float* __restrict__ bv, float* __restrict__ bqkv)
{
    int l = blockIdx.x;
    for (int n = threadIdx.x; n < QKVS; n += 256) {
        float v;
        if (n < H_)            v = bq[l * H_ + n];
        else if (n < 2 * H_)   v = bk[l * H_ + n - H_];
        else                   v = bv[l * H_ + n - 2 * H_];
        bqkv[l * QKVS + n] = v;
    }
}

// ---------------- embedding + LN ----------------
__global__ __launch_bounds__(256) void embed_ln_kernel(
    const float* __restrict__ WE, const float* __restrict__ PE,
    const float* __restrict__ g, const float* __restrict__ be,
    const int* __restrict__ ids,
    float* __restrict__ out, bf16* __restrict__ ohi, bf16* __restrict__ olo)
{
    int t = blockIdx.x;
    int s = t & (S_ - 1);
    int tid = threadIdx.x;
    int id = ids[t];
    float v[3];
    #pragma unroll
    for (int i = 0; i < 3; i++) {
        int c = tid + i * 256;
        v[i] = WE[(size_t)id * H_ + c] + PE[(size_t)s * H_ + c];
    }
    float ssum = block_reduce_sum(v[0] + v[1] + v[2]);
    float m = ssum * (1.f / H_);
    float sq = 0.f;
    #pragma unroll
    for (int i = 0; i < 3; i++) { float d = v[i] - m; sq += d * d; }
    float vs = block_reduce_sum(sq);
    float rs = rsqrtf(vs * (1.f / H_) + 1e-5f);
    #pragma unroll
    for (int i = 0; i < 3; i++) {
        int c = tid + i * 256;
        float y = (v[i] - m) * rs * g[c] + be[c];
        size_t o = (size_t)t * H_ + c;
        out[o] = y;
        bf16 hi, lo; split_bf16(y, hi, lo);
        ohi[o] = hi; olo[o] = lo;
    }
}

// ---------------- residual add + LN (in-place on h) ----------------
__global__ __launch_bounds__(256) void add_ln_kernel(
    float* __restrict__ h, const float* __restrict__ r,
    const float* __restrict__ g, const float* __restrict__ be,
    bf16* __restrict__ ohi, bf16* __restrict__ olo)
{
    int t = blockIdx.x;
    int tid = threadIdx.x;
    float v[3];
    #pragma unroll
    for (int i = 0; i < 3; i++) {
        int c = tid + i * 256;
        v[i] = h[(size_t)t * H_ + c] + r[(size_t)t * H_ + c];
    }
    float ssum = block_reduce_sum(v[0] + v[1] + v[2]);
    float m = ssum * (1.f / H_);
    float sq = 0.f;
    #pragma unroll
    for (int i = 0; i < 3; i++) { float d = v[i] - m; sq += d * d; }
    float vs = block_reduce_sum(sq);
    float rs = rsqrtf(vs * (1.f / H_) + 1e-5f);
    #pragma unroll
    for (int i = 0; i < 3; i++) {
        int c = tid + i * 256;
        float y = (v[i] - m) * rs * g[c] + be[c];
        size_t o = (size_t)t * H_ + c;
        h[o] = y;
        bf16 hi, lo; split_bf16(y, hi, lo);
        ohi[o] = hi; olo[o] = lo;
    }
}

// ================= bf16x3 tensor-core GEMM (ldmatrix) =================
#define PSTR 20                 // uint32 per tile row (16 data + 4 pad)
#define STG  (128 * PSTR)       // uint32 per tile stage

__global__ __launch_bounds__(256) void tgemm_kernel(
    const bf16* __restrict__ Ah, const bf16* __restrict__ Al,
    const bf16* __restrict__ Bh, const bf16* __restrict__ Bl,
    const float* __restrict__ bias,
    float* __restrict__ Cf, bf16* __restrict__ Ch, bf16* __restrict__ Cl,
    int M, int N, int K, int mode)
{
    extern __shared__ uint32_t smem_u[];

    const int tid  = threadIdx.x;
    const int warp = tid >> 5;
    const int lane = tid & 31;
    const int m0 = blockIdx.y * 128;
    const int n0 = blockIdx.x * 128;
    const int wm = (warp >> 1) * 32;
    const int wn = (warp & 1) * 64;
    const int grp = lane >> 2;
    const int tig = lane & 3;
    const uint32_t smbase = (uint32_t)__cvta_generic_to_shared(smem_u);

    // ldmatrix lane geometry
    const int aRow = wm + (lane & 7) + ((lane >> 3) & 1) * 8;   // + mi*16
    const int aBlk = lane >> 4;                                  // + st*2
    const int bRow = wn + (lane & 7) + (lane >> 4) * 8;          // + t*16
    const int bBlk = (lane >> 3) & 1;                            // + st*2

    float acc[2][8][4];
    #pragma unroll
    for (int mi = 0; mi < 2; mi++)
        #pragma unroll
        for (int ni = 0; ni < 8; ni++)
            #pragma unroll
            for (int c = 0; c < 4; c++) acc[mi][ni][c] = 0.f;

    const int KT = K >> 5;     // BK = 32

    #define LOAD_STAGE(s, k0)                                                          \
    {                                                                                  \
        _Pragma("unroll")                                                              \
        for (int r = 0; r < 2; r++) {                                                  \
            int idx = tid + r * 256;                                                   \
            int row = idx >> 2, c = idx & 3;                                           \
            uint32_t doff = ((s) * STG + row * PSTR + c * 4) * 4;                      \
            size_t aoff = (size_t)(m0 + row) * K + (k0) + c * 8;                       \
            size_t boff = (size_t)(n0 + row) * K + (k0) + c * 8;                       \
            cp_async16(smbase + (0 * 2 * STG) * 4 + doff, Ah + aoff);                  \
            cp_async16(smbase + (1 * 2 * STG) * 4 + doff, Al + aoff);                  \
            cp_async16(smbase + (2 * 2 * STG) * 4 + doff, Bh + boff);                  \
            cp_async16(smbase + (3 * 2 * STG) * 4 + doff, Bl + boff);                  \
        }                                                                              \
        cp_async_commit();                                                             \
    }

    LOAD_STAGE(0, 0)

    int buf = 0;
    for (int kt = 0; kt < KT; kt++) {
        cp_async_wait0();
        __syncthreads();
        if (kt + 1 < KT) {
            LOAD_STAGE(buf ^ 1, (kt + 1) << 5)
        }

        #pragma unroll
        for (int st = 0; st < 2; st++) {
            uint32_t ah_[2][4], al_[2][4];
            #pragma unroll
            for (int mi = 0; mi < 2; mi++) {
                uint32_t ad = smbase + (buf * STG + (aRow + mi * 16) * PSTR) * 4
                            + (st * 2 + aBlk) * 16;
                ldsm_x4(ah_[mi][0], ah_[mi][1], ah_[mi][2], ah_[mi][3], ad);
                ldsm_x4(al_[mi][0], al_[mi][1], al_[mi][2], al_[mi][3],
                        ad + 2 * STG * 4);
            }
            uint32_t bh_[8][2], bl_[8][2];
            #pragma unroll
            for (int t = 0; t < 4; t++) {
                uint32_t ad = smbase + (buf * STG + (bRow + t * 16) * PSTR) * 4
                            + (st * 2 + bBlk) * 16 + 4 * STG * 4;
                ldsm_x4(bh_[2*t][0], bh_[2*t][1], bh_[2*t+1][0], bh_[2*t+1][1], ad);
                ldsm_x4(bl_[2*t][0], bl_[2*t][1], bl_[2*t+1][0], bl_[2*t+1][1],
                        ad + 2 * STG * 4);
            }
            #pragma unroll
            for (int mi = 0; mi < 2; mi++) {
                #pragma unroll
                for (int ni = 0; ni < 8; ni++) {
                    mma_bf16(acc[mi][ni], al_[mi][0], al_[mi][1], al_[mi][2], al_[mi][3],
                             bh_[ni][0], bh_[ni][1]);
                    mma_bf16(acc[mi][ni], ah_[mi][0], ah_[mi][1], ah_[mi][2], ah_[mi][3],
                             bl_[ni][0], bl_[ni][1]);
                    mma_bf16(acc[mi][ni], ah_[mi][0], ah_[mi][1], ah_[mi][2], ah_[mi][3],
                             bh_[ni][0], bh_[ni][1]);
                }
            }
        }
        __syncthreads();
        buf ^= 1;
    }

    // ---- epilogue ----
    #pragma unroll
    for (int mi = 0; mi < 2; mi++) {
        int row0 = m0 + wm + mi * 16 + grp;
        #pragma unroll
        for (int ni = 0; ni < 8; ni++) {
            int col = n0 + wn + ni * 8 + tig * 2;
            float b0 = bias[col], b1 = bias[col + 1];
            float v0 = acc[mi][ni][0] + b0;
            float v1 = acc[mi][ni][1] + b1;
            float v2 = acc[mi][ni][2] + b0;
            float v3 = acc[mi][ni][3] + b1;
            if (mode == 1) {
                v0 = 0.5f * v0 * (1.0f + erff(v0 * 0.70710678118654752f));
                v1 = 0.5f * v1 * (1.0f + erff(v1 * 0.70710678118654752f));
                v2 = 0.5f * v2 * (1.0f + erff(v2 * 0.70710678118654752f));
                v3 = 0.5f * v3 * (1.0f + erff(v3 * 0.70710678118654752f));
                size_t o0 = (size_t)row0 * N + col;
                size_t o1 = (size_t)(row0 + 8) * N + col;
                bf16 hi, lo;
                split_bf16(v0, hi, lo); Ch[o0]     = hi; Cl[o0]     = lo;
                split_bf16(v1, hi, lo); Ch[o0 + 1] = hi; Cl[o0 + 1] = lo;
                split_bf16(v2, hi, lo); Ch[o1]     = hi; Cl[o1]     = lo;
                split_bf16(v3, hi, lo); Ch[o1 + 1] = hi; Cl[o1 + 1] = lo;
            } else {
                *(float2*)(Cf + (size_t)row0 * N + col)       = make_float2(v0, v1);
                *(float2*)(Cf + (size_t)(row0 + 8) * N + col) = make_float2(v2, v3);
            }
        }
    }
}

// ================= tensor-core local attention =================
// q-tile 128 (8 warps x m16), key tiles of 64, DH=64.
#define QSTR 36   // uint32 per row (64 bf16 + 8 pad)
#define ATT_SMEM ((2 * 128 * QSTR + 4 * 64 * QSTR + 64) * 4)

__global__ __launch_bounds__(256, 1) void attn_tc_kernel(
    const float* __restrict__ QKV, const int* __restrict__ amask,
    bf16* __restrict__ Ohi, bf16* __restrict__ Olo)
{
    extern __shared__ uint32_t sm[];
    const int OQH = 0;
    const int OQL = OQH + 128 * QSTR;
    const int OKH = OQL + 128 * QSTR;
    const int OKL = OKH + 64 * QSTR;
    const int OVH = OKL + 64 * QSTR;
    const int OVL = OVH + 64 * QSTR;
    const int OMF = OVL + 64 * QSTR;
    bf16* smb = (bf16*)sm;
    float* mf = (float*)(sm + OMF);

    const int q0 = blockIdx.x * 128;
    const int hh = blockIdx.y;
    const int b  = blockIdx.z;
    const int tid = threadIdx.x, warp = tid >> 5, lane = tid & 31;
    const int grp = lane >> 2, tig = lane & 3;
    const uint32_t base = (uint32_t)__cvta_generic_to_shared(sm);
    const unsigned FULL = 0xffffffffu;

    // ---- stage Q (x0.125, hi/lo split) ----
    for (int idx = tid; idx < 128 * 64; idx += 256) {
        int r = idx >> 6, d = idx & 63;
        float x = QKV[(size_t)(b * S_ + q0 + r) * QKVS + hh * DH_ + d] * 0.125f;
        bf16 hi, lo; split_bf16(x, hi, lo);
        smb[OQH * 2 + r * (QSTR * 2) + d] = hi;
        smb[OQL * 2 + r * (QSTR * 2) + d] = lo;
    }
    __syncthreads();

    // ---- extract Q fragments (held in registers for whole kernel) ----
    uint32_t qfh[4][4], qfl[4][4];
    {
        int arow = warp * 16 + (lane & 7) + ((lane >> 3) & 1) * 8;
        int ablk = lane >> 4;
        #pragma unroll
        for (int st = 0; st < 4; st++) {
            uint32_t ad = base + (OQH + arow * QSTR) * 4 + (st * 2 + ablk) * 16;
            ldsm_x4(qfh[st][0], qfh[st][1], qfh[st][2], qfh[st][3], ad);
            ldsm_x4(qfl[st][0], qfl[st][1], qfl[st][2], qfl[st][3],
                    ad + (OQL - OQH) * 4);
        }
    }

    float o[8][4];
    #pragma unroll
    for (int ni = 0; ni < 8; ni++)
        #pragma unroll
        for (int c = 0; c < 4; c++) o[ni][c] = 0.f;
    float m0 = -1e30f, m1 = -1e30f, l0 = 0.f, l1 = 0.f;

    const int brow = (lane & 7) + (lane >> 4) * 8;          // K ldsm rows
    const int bblk = (lane >> 3) & 1;
    const int vrow = (lane & 7) + ((lane >> 3) & 1) * 8;    // V trans-ldsm rows
    const int vblk = lane >> 4;
    const int qg0 = q0 + warp * 16 + grp;
    const int qg1 = qg0 + 8;

    for (int kt = 0; kt < 10; kt++) {
        const int ks = q0 - 256 + kt * 64;
        if (ks + 64 <= 0 || ks >= S_) continue;
        __syncthreads();
        // ---- stage K, V tiles (hi/lo split), mask ----
        for (int idx = tid; idx < 64 * 64; idx += 256) {
            int c = idx >> 6, d = idx & 63;
            int kg = ks + c;
            bool in = (kg >= 0 && kg < S_);
            float kx = in ? QKV[(size_t)(b * S_ + kg) * QKVS + H_ + hh * DH_ + d] : 0.f;
            float vx = in ? QKV[(size_t)(b * S_ + kg) * QKVS + 2 * H_ + hh * DH_ + d] : 0.f;
            bf16 hi, lo;
            int ro = c * (QSTR * 2) + d;
            split_bf16(kx, hi, lo);
            smb[OKH * 2 + ro] = hi; smb[OKL * 2 + ro] = lo;
            split_bf16(vx, hi, lo);
            smb[OVH * 2 + ro] = hi; smb[OVL * 2 + ro] = lo;
        }
        if (tid < 64) {
            int kg = ks + tid;
            mf[tid] = (kg >= 0 && kg < S_ && amask[b * S_ + kg] > 0) ? 0.f : -1e9f;
        }
        __syncthreads();

        // ---- S = Q K^T (3-term bf16) ----
        float s[8][4];
        #pragma unroll
        for (int ni = 0; ni < 8; ni++)
            #pragma unroll
            for (int c = 0; c < 4; c++) s[ni][c] = 0.f;
        #pragma unroll
        for (int st = 0; st < 4; st++) {
            uint32_t kbh[8][2], kbl[8][2];
            #pragma unroll
            for (int t = 0; t < 4; t++) {
                uint32_t ad = base + (OKH + (t * 16 + brow) * QSTR) * 4
                            + (st * 2 + bblk) * 16;
                ldsm_x4(kbh[2*t][0], kbh[2*t][1], kbh[2*t+1][0], kbh[2*t+1][1], ad);
                ldsm_x4(kbl[2*t][0], kbl[2*t][1], kbl[2*t+1][0], kbl[2*t+1][1],
                        ad + (OKL - OKH) * 4);
            }
            #pragma unroll
            for (int ni = 0; ni < 8; ni++) {
                mma_bf16(s[ni], qfl[st][0], qfl[st][1], qfl[st][2], qfl[st][3],
                         kbh[ni][0], kbh[ni][1]);
                mma_bf16(s[ni], qfh[st][0], qfh[st][1], qfh[st][2], qfh[st][3],
                         kbl[ni][0], kbl[ni][1]);
                mma_bf16(s[ni], qfh[st][0], qfh[st][1], qfh[st][2], qfh[st][3],
                         kbh[ni][0], kbh[ni][1]);
            }
        }

        // ---- mask + online softmax ----
        float tmax0 = -1e30f, tmax1 = -1e30f;
        #pragma unroll
        for (int ni = 0; ni < 8; ni++) {
            int kl0 = ni * 8 + 2 * tig;
            float mv0 = mf[kl0], mv1 = mf[kl0 + 1];
            int kg0 = ks + kl0;
            int d00 = kg0 - qg0, d01 = d00 + 1;
            int d10 = kg0 - qg1, d11 = d10 + 1;
            float x0 = (d00 >= -WIN_ && d00 <= WIN_) ? s[ni][0] + mv0 : -1e9f;
            float x1 = (d01 >= -WIN_ && d01 <= WIN_) ? s[ni][1] + mv1 : -1e9f;
            float x2 = (d10 >= -WIN_ && d10 <= WIN_) ? s[ni][2] + mv0 : -1e9f;
            float x3 = (d11 >= -WIN_ && d11 <= WIN_) ? s[ni][3] + mv1 : -1e9f;
            s[ni][0] = x0; s[ni][1] = x1; s[ni][2] = x2; s[ni][3] = x3;
            tmax0 = fmaxf(tmax0, fmaxf(x0, x1));
            tmax1 = fmaxf(tmax1, fmaxf(x2, x3));
        }
        tmax0 = fmaxf(tmax0, __shfl_xor_sync(FULL, tmax0, 1));
        tmax0 = fmaxf(tmax0, __shfl_xor_sync(FULL, tmax0, 2));
        tmax1 = fmaxf(tmax1, __shfl_xor_sync(FULL, tmax1, 1));
        tmax1 = fmaxf(tmax1, __shfl_xor_sync(FULL, tmax1, 2));
        float mn0 = fmaxf(m0, tmax0), mn1 = fmaxf(m1, tmax1);
        float sc0 = __expf(m0 - mn0), sc1 = __expf(m1 - mn1);
        float ps0 = 0.f, ps1 = 0.f;
        #pragma unroll
        for (int ni = 0; ni < 8; ni++) {
            s[ni][0] = __expf(s[ni][0] - mn0);
            s[ni][1] = __expf(s[ni][1] - mn0);
            s[ni][2] = __expf(s[ni][2] - mn1);
            s[ni][3] = __expf(s[ni][3] - mn1);
            ps0 += s[ni][0] + s[ni][1];
            ps1 += s[ni][2] + s[ni][3];
        }
        ps0 += __shfl_xor_sync(FULL, ps0, 1);
        ps0 += __shfl_xor_sync(FULL, ps0, 2);
        ps1 += __shfl_xor_sync(FULL, ps1, 1);
        ps1 += __shfl_xor_sync(FULL, ps1, 2);
        l0 = l0 * sc0 + ps0;
        l1 = l1 * sc1 + ps1;
        m0 = mn0; m1 = mn1;
        #pragma unroll
        for (int ni = 0; ni < 8; ni++) {
            o[ni][0] *= sc0; o[ni][1] *= sc0;
            o[ni][2] *= sc1; o[ni][3] *= sc1;
        }

        // ---- pack P fragments (hi/lo split) ----
        uint32_t pah[4][4], pal[4][4];
        #pragma unroll
        for (int j = 0; j < 4; j++) {
            packsplit(s[2*j][0],   s[2*j][1],   pah[j][0], pal[j][0]);
            packsplit(s[2*j][2],   s[2*j][3],   pah[j][1], pal[j][1]);
            packsplit(s[2*j+1][0], s[2*j+1][1], pah[j][2], pal[j][2]);
            packsplit(s[2*j+1][2], s[2*j+1][3], pah[j][3], pal[j][3]);
        }

        // ---- O += P V (3-term, V via trans-ldmatrix) ----
        #pragma unroll
        for (int j = 0; j < 4; j++) {
            uint32_t vbh[8][2], vbl[8][2];
            #pragma unroll
            for (int t = 0; t < 4; t++) {
                uint32_t ad = base + (OVH + (j * 16 + vrow) * QSTR) * 4
                            + (2 * t + vblk) * 16;
                ldsm_x4_t(vbh[2*t][0], vbh[2*t][1], vbh[2*t+1][0], vbh[2*t+1][1], ad);
                ldsm_x4_t(vbl[2*t][0], vbl[2*t][1], vbl[2*t+1][0], vbl[2*t+1][1],
                          ad + (OVL - OVH) * 4);
            }
            #pragma unroll
            for (int ni = 0; ni < 8; ni++) {
                mma_bf16(o[ni], pal[j][0], pal[j][1], pal[j][2], pal[j][3],
                         vbh[ni][0], vbh[ni][1]);
                mma_bf16(o[ni], pah[j][0], pah[j][1], pah[j][2], pah[j][3],
                         vbl[ni][0], vbl[ni][1]);
                mma_bf16(o[ni], pah[j][0], pah[j][1], pah[j][2], pah[j][3],
                         vbh[ni][0], vbh[ni][1]);
            }
        }
    }

    // ---- write output (hi/lo bf16) ----
    float inv0 = 1.f / l0, inv1 = 1.f / l1;
    #pragma unroll
    for (int ni = 0; ni < 8; ni++) {
        int dcol = hh * DH_ + ni * 8 + 2 * tig;
        size_t o0 = (size_t)(b * S_ + qg0) * H_ + dcol;
        size_t o1 = (size_t)(b * S_ + qg1) * H_ + dcol;
        uint32_t ph, pl;
        packsplit(o[ni][0] * inv0, o[ni][1] * inv0, ph, pl);
        *(uint32_t*)(Ohi + o0) = ph;
        *(uint32_t*)(Olo + o0) = pl;
        packsplit(o[ni][2] * inv1, o[ni][3] * inv1, ph, pl);
        *(uint32_t*)(Ohi + o1) = ph;
        *(uint32_t*)(Olo + o1) = pl;
    }
}

// ---------------- pooling head ----------------
__global__ __launch_bounds__(256) void attn_score_kernel(
    const float* __restrict__ h, const float* __restrict__ aw, float* __restrict__ sc)
{
    int t = blockIdx.x;
    int tid = threadIdx.x;
    float acc = 0.f;
    #pragma unroll
    for (int i = 0; i < 3; i++) {
        int c = tid + i * 256;
        acc += h[(size_t)t * H_ + c] * aw[c];
    }
    float s = block_reduce_sum(acc);
    if (tid == 0) sc[t] = s;
}

__global__ __launch_bounds__(256) void softmax_s_kernel(
    const float* __restrict__ sc, float* __restrict__ pr)
{
    int b = blockIdx.x;
    int tid = threadIdx.x;
    float v[4];
    float mx = -1e30f;
    #pragma unroll
    for (int i = 0; i < 4; i++) {
        v[i] = sc[b * S_ + tid + i * 256];
        mx = fmaxf(mx, v[i]);
    }
    mx = block_reduce_max(mx);
    float e[4], ps = 0.f;
    #pragma unroll
    for (int i = 0; i < 4; i++) { e[i] = __expf(v[i] - mx); ps += e[i]; }
    float tot = block_reduce_sum(ps);
    float inv = 1.f / tot;
    #pragma unroll
    for (int i = 0; i < 4; i++) pr[b * S_ + tid + i * 256] = e[i] * inv;
}

__global__ __launch_bounds__(256) void pool_kernel(
    const float* __restrict__ h, const float* __restrict__ pr, float* __restrict__ pooled)
{
    int d = blockIdx.x * 256 + threadIdx.x;
    int b = blockIdx.y;
    float acc = 0.f;
    for (int s = 0; s < S_; s++) {
        acc += h[((size_t)(b * S_ + s)) * H_ + d] * pr[b * S_ + s];
    }
    pooled[b * H_ + d] = acc;
}

__global__ __launch_bounds__(256) void final_kernel(
    const float* __restrict__ pooled, const float* __restrict__ Wc,
    const float* __restrict__ bc, float* __restrict__ out)
{
    int b = blockIdx.x;
    int tid = threadIdx.x;
    float acc = 0.f;
    #pragma unroll
    for (int i = 0; i < 3; i++) {
        int c = tid + i * 256;
        acc += pooled[b * H_ + c] * Wc[c];
    }
    float s = block_reduce_sum(acc);
    if (tid == 0) out[b] = s + bc[0];
}

// ---------------- host launcher ----------------
extern "C" void kernel_launch(void* const* d_in, const int* in_sizes, int n_in,
                              void* d_out, int out_size)
{
    (void)in_sizes; (void)n_in; (void)out_size;
    const float* WE   = (const float*)d_in[0];
    const float* PE   = (const float*)d_in[1];
    const float* Eg   = (const float*)d_in[2];
    const float* Eb   = (const float*)d_in[3];
    const float* Wq   = (const float*)d_in[4];
    const float* bq   = (const float*)d_in[5];
    const float* Wk   = (const float*)d_in[6];
    const float* bk   = (const float*)d_in[7];
    const float* Wv   = (const float*)d_in[8];
    const float* bv   = (const float*)d_in[9];
    const float* Wo   = (const float*)d_in[10];
    const float* bo   = (const float*)d_in[11];
    const float* g1   = (const float*)d_in[12];
    const float* beta1= (const float*)d_in[13];
    const float* W1   = (const float*)d_in[14];
    const float* b1   = (const float*)d_in[15];
    const float* W2   = (const float*)d_in[16];
    const float* b2   = (const float*)d_in[17];
    const float* g2   = (const float*)d_in[18];
    const float* beta2= (const float*)d_in[19];
    const float* aw   = (const float*)d_in[20];
    const float* Wc   = (const float*)d_in[21];
    const float* bc   = (const float*)d_in[22];
    const int*   ids  = (const int*)d_in[23];
    const int*   am   = (const int*)d_in[24];
    float* out = (float*)d_out;

    bf16 *wqkv_hi, *wqkv_lo, *wot_hi, *wot_lo, *w1t_hi, *w1t_lo, *w2t_hi, *w2t_lo;
    bf16 *h_hi, *h_lo, *a_hi, *a_lo, *f_hi, *f_lo;
    float *bqkv, *h, *qkv, *r, *sc, *pr, *pooled;
    cudaGetSymbolAddress((void**)&wqkv_hi, g_wqkv_hi);
    cudaGetSymbolAddress((void**)&wqkv_lo, g_wqkv_lo);
    cudaGetSymbolAddress((void**)&wot_hi,  g_wot_hi);
    cudaGetSymbolAddress((void**)&wot_lo,  g_wot_lo);
    cudaGetSymbolAddress((void**)&w1t_hi,  g_w1t_hi);
    cudaGetSymbolAddress((void**)&w1t_lo,  g_w1t_lo);
    cudaGetSymbolAddress((void**)&w2t_hi,  g_w2t_hi);
    cudaGetSymbolAddress((void**)&w2t_lo,  g_w2t_lo);
    cudaGetSymbolAddress((void**)&bqkv,    g_bqkv);
    cudaGetSymbolAddress((void**)&h,       g_h);
    cudaGetSymbolAddress((void**)&h_hi,    g_h_hi);
    cudaGetSymbolAddress((void**)&h_lo,    g_h_lo);
    cudaGetSymbolAddress((void**)&qkv,     g_qkv);
    cudaGetSymbolAddress((void**)&a_hi,    g_a_hi);
    cudaGetSymbolAddress((void**)&a_lo,    g_a_lo);
    cudaGetSymbolAddress((void**)&f_hi,    g_f_hi);
    cudaGetSymbolAddress((void**)&f_lo,    g_f_lo);
    cudaGetSymbolAddress((void**)&r,       g_r);
    cudaGetSymbolAddress((void**)&sc,      g_sc);
    cudaGetSymbolAddress((void**)&pr,      g_pr);
    cudaGetSymbolAddress((void**)&pooled,  g_pool);

    cudaFuncSetAttribute(tgemm_kernel,
                         cudaFuncAttributeMaxDynamicSharedMemorySize, 8 * STG * 4);
    cudaFuncSetAttribute(attn_tc_kernel,
                         cudaFuncAttributeMaxDynamicSharedMemorySize, ATT_SMEM);

    // ---- weight pre-pass: transpose + split (batched over layers) ----
    dim3 wb(256);
    dim3 gHH(H_ / 32, H_ / 32, L_);
    dim3 gHF(FF_ / 32, H_ / 32, L_);
    dim3 gFH(H_ / 32, FF_ / 32, L_);
    wsplit_kernel<<<gHH, wb>>>(Wq, wqkv_hi, wqkv_lo, H_, H_,
                               (size_t)H_ * H_, (size_t)QKVS * H_);
    wsplit_kernel<<<gHH, wb>>>(Wk, wqkv_hi + (size_t)H_ * H_,
                               wqkv_lo + (size_t)H_ * H_, H_, H_,
                               (size_t)H_ * H_, (size_t)QKVS * H_);
    wsplit_kernel<<<gHH, wb>>>(Wv, wqkv_hi + (size_t)2 * H_ * H_,
                               wqkv_lo + (size_t)2 * H_ * H_, H_, H_,
                               (size_t)H_ * H_, (size_t)QKVS * H_);
    wsplit_kernel<<<gHH, wb>>>(Wo, wot_hi, wot_lo, H_, H_,
                               (size_t)H_ * H_, (size_t)H_ * H_);
    wsplit_kernel<<<gHF, wb>>>(W1, w1t_hi, w1t_lo, H_, FF_,
                               (size_t)H_ * FF_, (size_t)FF_ * H_);
    wsplit_kernel<<<gFH, wb>>>(W2, w2t_hi, w2t_lo, FF_, H_,
                               (size_t)FF_ * H_, (size_t)H_ * FF_);
    bias_concat_kernel<<<L_, 256>>>(bq, bk, bv, bqkv);

    embed_ln_kernel<<<BS_, 256>>>(WE, PE, Eg, Eb, ids, h, h_hi, h_lo);

    const size_t SMEMB = 8 * STG * 4;
    dim3 gQKV(QKVS / 128, BS_ / 128);
    dim3 gO(H_ / 128, BS_ / 128);
    dim3 gW1(FF_ / 128, BS_ / 128);
    dim3 gattn(S_ / 128, NH_, B_);

    for (int l = 0; l < L_; l++) {
        tgemm_kernel<<<gQKV, 256, SMEMB>>>(h_hi, h_lo,
            wqkv_hi + (size_t)l * QKVS * H_, wqkv_lo + (size_t)l * QKVS * H_,
            bqkv + l * QKVS, qkv, nullptr, nullptr, BS_, QKVS, H_, 0);

        attn_tc_kernel<<<gattn, 256, ATT_SMEM>>>(qkv, am, a_hi, a_lo);

        tgemm_kernel<<<gO, 256, SMEMB>>>(a_hi, a_lo,
            wot_hi + (size_t)l * H_ * H_, wot_lo + (size_t)l * H_ * H_,
            bo + l * H_, r, nullptr, nullptr, BS_, H_, H_, 0);
        add_ln_kernel<<<BS_, 256>>>(h, r, g1 + l * H_, beta1 + l * H_, h_hi, h_lo);

        tgemm_kernel<<<gW1, 256, SMEMB>>>(h_hi, h_lo,
            w1t_hi + (size_t)l * FF_ * H_, w1t_lo + (size_t)l * FF_ * H_,
            b1 + l * FF_, nullptr, f_hi, f_lo, BS_, FF_, H_, 1);

        tgemm_kernel<<<gO, 256, SMEMB>>>(f_hi, f_lo,
            w2t_hi + (size_t)l * H_ * FF_, w2t_lo + (size_t)l * H_ * FF_,
            b2 + l * H_, r, nullptr, nullptr, BS_, H_, FF_, 0);
        add_ln_kernel<<<BS_, 256>>>(h, r, g2 + l * H_, beta2 + l * H_, h_hi, h_lo);
    }

    attn_score_kernel<<<BS_, 256>>>(h, aw, sc);
    softmax_s_kernel<<<B_, 256>>>(sc, pr);
    pool_kernel<<<dim3(H_ / 256, B_), 256>>>(h, pr, pooled);
    final_kernel<<<B_, 256>>>(pooled, Wc, bc, out);
}

// round 8
// speedup vs baseline: 2.8624x; 1.0608x over previous
#include <cuda_runtime.h>
#include <cuda_bf16.h>
#include <cstdint>
#include <math.h>

#define L_  12
#define NH_ 12
#define DH_ 64
#define H_  768
#define FF_ 3072
#define S_  1024
#define B_  4
#define BS_ (B_ * S_)   // 4096
#define WIN_ 256
#define QKVS 2304       // fused qkv row stride

typedef __nv_bfloat16 bf16;

// ---------------- scratch (no allocations allowed) ----------------
__device__ bf16 g_wqkv_hi[L_ * QKVS * H_];
__device__ bf16 g_wqkv_lo[L_ * QKVS * H_];
__device__ bf16 g_wot_hi [L_ * H_ * H_];
__device__ bf16 g_wot_lo [L_ * H_ * H_];
__device__ bf16 g_w1t_hi [L_ * FF_ * H_];
__device__ bf16 g_w1t_lo [L_ * FF_ * H_];
__device__ bf16 g_w2t_hi [L_ * H_ * FF_];
__device__ bf16 g_w2t_lo [L_ * H_ * FF_];
__device__ float g_bqkv  [L_ * QKVS];

__device__ float g_h   [BS_ * H_];
__device__ bf16  g_h_hi[BS_ * H_];
__device__ bf16  g_h_lo[BS_ * H_];
__device__ float g_qkv [BS_ * QKVS];
__device__ bf16  g_a_hi[BS_ * H_];
__device__ bf16  g_a_lo[BS_ * H_];
__device__ bf16  g_f_hi[BS_ * FF_];
__device__ bf16  g_f_lo[BS_ * FF_];
__device__ float g_r   [BS_ * H_];
__device__ float g_sc  [BS_];
__device__ float g_pr  [BS_];
__device__ float g_pool[B_ * H_];

__device__ __forceinline__ void split_bf16(float x, bf16& hi, bf16& lo) {
    hi = __float2bfloat16_rn(x);
    lo = __float2bfloat16_rn(x - __bfloat162float(hi));
}

// ---------------- low-level helpers ----------------
__device__ __forceinline__ void cp_async16(uint32_t smem_addr, const void* gptr) {
    asm volatile("cp.async.cg.shared.global [%0], [%1], 16;\n"
                 :: "r"(smem_addr), "l"(gptr));
}
__device__ __forceinline__ void cp_async_commit() {
    asm volatile("cp.async.commit_group;\n");
}
__device__ __forceinline__ void cp_async_wait0() {
    asm volatile("cp.async.wait_group 0;\n");
}
__device__ __forceinline__ void ldsm_x4(uint32_t& r0, uint32_t& r1, uint32_t& r2,
                                        uint32_t& r3, uint32_t a) {
    asm volatile("ldmatrix.sync.aligned.m8n8.x4.shared.b16 {%0,%1,%2,%3}, [%4];"
                 : "=r"(r0), "=r"(r1), "=r"(r2), "=r"(r3) : "r"(a));
}
__device__ __forceinline__ void ldsm_x4_t(uint32_t& r0, uint32_t& r1, uint32_t& r2,
                                          uint32_t& r3, uint32_t a) {
    asm volatile("ldmatrix.sync.aligned.m8n8.x4.trans.shared.b16 {%0,%1,%2,%3}, [%4];"
                 : "=r"(r0), "=r"(r1), "=r"(r2), "=r"(r3) : "r"(a));
}
__device__ __forceinline__ void mma_bf16(
    float* acc, uint32_t a0, uint32_t a1, uint32_t a2, uint32_t a3,
    uint32_t b0, uint32_t b1)
{
    asm volatile(
        "mma.sync.aligned.m16n8k16.row.col.f32.bf16.bf16.f32 "
        "{%0,%1,%2,%3}, {%4,%5,%6,%7}, {%8,%9}, {%0,%1,%2,%3};\n"
        : "+f"(acc[0]), "+f"(acc[1]), "+f"(acc[2]), "+f"(acc[3])
        : "r"(a0), "r"(a1), "r"(a2), "r"(a3), "r"(b0), "r"(b1));
}
__device__ __forceinline__ void packsplit(float a, float b, uint32_t& ph, uint32_t& pl) {
    bf16 ah = __float2bfloat16_rn(a), bh = __float2bfloat16_rn(b);
    float al = a - __bfloat162float(ah), bl = b - __bfloat162float(bh);
    ph = ((uint32_t)__bfloat16_as_ushort(bh) << 16) | (uint32_t)__bfloat16_as_ushort(ah);
    pl = ((uint32_t)__bfloat16_as_ushort(__float2bfloat16_rn(bl)) << 16)
       |  (uint32_t)__bfloat16_as_ushort(__float2bfloat16_rn(al));
}

// ---------------- reduction helpers ----------------
__device__ __forceinline__ float block_reduce_sum(float v) {
    __shared__ float red[32];
    int lane = threadIdx.x & 31, wid = threadIdx.x >> 5;
    #pragma unroll
    for (int o = 16; o; o >>= 1) v += __shfl_xor_sync(0xffffffffu, v, o);
    if (lane == 0) red[wid] = v;
    __syncthreads();
    int nw = (blockDim.x + 31) >> 5;
    v = (threadIdx.x < nw) ? red[threadIdx.x] : 0.f;
    if (wid == 0) {
        #pragma unroll
        for (int o = 16; o; o >>= 1) v += __shfl_xor_sync(0xffffffffu, v, o);
    }
    if (threadIdx.x == 0) red[0] = v;
    __syncthreads();
    v = red[0];
    __syncthreads();
    return v;
}

__device__ __forceinline__ float block_reduce_max(float v) {
    __shared__ float red[32];
    int lane = threadIdx.x & 31, wid = threadIdx.x >> 5;
    #pragma unroll
    for (int o = 16; o; o >>= 1) v = fmaxf(v, __shfl_xor_sync(0xffffffffu, v, o));
    if (lane == 0) red[wid] = v;
    __syncthreads();
    int nw = (blockDim.x + 31) >> 5;
    v = (threadIdx.x < nw) ? red[threadIdx.x] : -1e30f;
    if (wid == 0) {
        #pragma unroll
        for (int o = 16; o; o >>= 1) v = fmaxf(v, __shfl_xor_sync(0xffffffffu, v, o));
    }
    if (threadIdx.x == 0) red[0] = v;
    __syncthreads();
    v = red[0];
    __syncthreads();
    return v;
}

// ---------------- weight transpose + hi/lo split ----------------
__global__ __launch_bounds__(256) void wsplit_kernel(
    const float* __restrict__ src, bf16* __restrict__ dhi, bf16* __restrict__ dlo,
    int K, int N, size_t srcStride, size_t dstStride)
{
    __shared__ float t[32][33];
    int l = blockIdx.z;
    src += (size_t)l * srcStride;
    dhi += (size_t)l * dstStride;
    dlo += (size_t)l * dstStride;
    int tx = threadIdx.x & 31, ty = threadIdx.x >> 5;
    int n0 = blockIdx.x * 32, k0 = blockIdx.y * 32;
    #pragma unroll
    for (int i = 0; i < 4; i++)
        t[ty + i * 8][tx] = src[(size_t)(k0 + ty + i * 8) * N + n0 + tx];
    __syncthreads();
    #pragma unroll
    for (int i = 0; i < 4; i++) {
        int r = ty + i * 8;
        float x = t[tx][r];
        bf16 hi, lo; split_bf16(x, hi, lo);
        size_t o = (size_t)(n0 + r) * K + k0 + tx;
        dhi[o] = hi; dlo[o] = lo;
    }
}

// QKV variant: z = l*3 + j picks Wq/Wk/Wv and packs into fused [QKVS][H] dst
__global__ __launch_bounds__(256) void wsplit_qkv_kernel(
    const float* __restrict__ Wq, const float* __restrict__ Wk,
    const float* __restrict__ Wv, bf16* __restrict__ dhi, bf16* __restrict__ dlo)
{
    __shared__ float t[32][33];
    int z = blockIdx.z;
    int l = z / 3, j = z % 3;
    const float* src = (j == 0 ? Wq : (j == 1 ? Wk : Wv)) + (size_t)l * H_ * H_;
    bf16* oh = dhi + (size_t)l * QKVS * H_ + (size_t)j * H_ * H_;
    bf16* ol = dlo + (size_t)l * QKVS * H_ + (size_t)j * H_ * H_;
    int tx = threadIdx.x & 31, ty = threadIdx.x >> 5;
    int n0 = blockIdx.x * 32, k0 = blockIdx.y * 32;
    #pragma unroll
    for (int i = 0; i < 4; i++)
        t[ty + i * 8][tx] = src[(size_t)(k0 + ty + i * 8) * H_ + n0 + tx];
    __syncthreads();
    #pragma unroll
    for (int i = 0; i < 4; i++) {
        int r = ty + i * 8;
        float x = t[tx][r];
        bf16 hi, lo; split_bf16(x, hi, lo);
        size_t o = (size_t)(n0 + r) * H_ + k0 + tx;
        oh[o] = hi; ol[o] = lo;
    }
}

// ---------------- embedding + LN (+ fused qkv-bias concat) ----------------
__global__ __launch_bounds__(256) void embed_ln_kernel(
    const float* __restrict__ WE, const float* __restrict__ PE,
    const float* __restrict__ g, const float* __restrict__ be,
    const int* __restrict__ ids,
    float* __restrict__ out, bf16* __restrict__ ohi, bf16* __restrict__ olo,
    const float* __restrict__ bq, const float* __restrict__ bk,
    const float* __restrict__ bv, float* __restrict__ bqkv)
{
    int t = blockIdx.x;
    int tid = threadIdx.x;
    if (t >= BS_) {   // qkv bias concat blocks
        int l = t - BS_;
        for (int n = tid; n < QKVS; n += 256) {
            float v;
            if (n < H_)          v = bq[l * H_ + n];
            else if (n < 2 * H_) v = bk[l * H_ + n - H_];
            else                 v = bv[l * H_ + n - 2 * H_];
            bqkv[l * QKVS + n] = v;
        }
        return;
    }
    int s = t & (S_ - 1);
    int id = ids[t];
    float v[3];
    #pragma unroll
    for (int i = 0; i < 3; i++) {
        int c = tid + i * 256;
        v[i] = WE[(size_t)id * H_ + c] + PE[(size_t)s * H_ + c];
    }
    float ssum = block_reduce_sum(v[0] + v[1] + v[2]);
    float m = ssum * (1.f / H_);
    float sq = 0.f;
    #pragma unroll
    for (int i = 0; i < 3; i++) { float d = v[i] - m; sq += d * d; }
    float vs = block_reduce_sum(sq);
    float rs = rsqrtf(vs * (1.f / H_) + 1e-5f);
    #pragma unroll
    for (int i = 0; i < 3; i++) {
        int c = tid + i * 256;
        float y = (v[i] - m) * rs * g[c] + be[c];
        size_t o = (size_t)t * H_ + c;
        out[o] = y;
        bf16 hi, lo; split_bf16(y, hi, lo);
        ohi[o] = hi; olo[o] = lo;
    }
}

// ---------------- residual add + LN (in-place on h) ----------------
__global__ __launch_bounds__(256) void add_ln_kernel(
    float* __restrict__ h, const float* __restrict__ r,
    const float* __restrict__ g, const float* __restrict__ be,
    bf16* __restrict__ ohi, bf16* __restrict__ olo)
{
    int t = blockIdx.x;
    int tid = threadIdx.x;
    float v[3];
    #pragma unroll
    for (int i = 0; i < 3; i++) {
        int c = tid + i * 256;
        v[i] = h[(size_t)t * H_ + c] + r[(size_t)t * H_ + c];
    }
    float ssum = block_reduce_sum(v[0] + v[1] + v[2]);
    float m = ssum * (1.f / H_);
    float sq = 0.f;
    #pragma unroll
    for (int i = 0; i < 3; i++) { float d = v[i] - m; sq += d * d; }
    float vs = block_reduce_sum(sq);
    float rs = rsqrtf(vs * (1.f / H_) + 1e-5f);
    #pragma unroll
    for (int i = 0; i < 3; i++) {
        int c = tid + i * 256;
        float y = (v[i] - m) * rs * g[c] + be[c];
        size_t o = (size_t)t * H_ + c;
        h[o] = y;
        bf16 hi, lo; split_bf16(y, hi, lo);
        ohi[o] = hi; olo[o] = lo;
    }
}

// ================= bf16x3 tensor-core GEMM (ldmatrix, term-major) ==========
#define PSTR 20                 // uint32 per tile row (16 data + 4 pad)
#define STG  (128 * PSTR)       // uint32 per tile stage

__global__ __launch_bounds__(256) void tgemm_kernel(
    const bf16* __restrict__ Ah, const bf16* __restrict__ Al,
    const bf16* __restrict__ Bh, const bf16* __restrict__ Bl,
    const float* __restrict__ bias,
    float* __restrict__ Cf, bf16* __restrict__ Ch, bf16* __restrict__ Cl,
    int M, int N, int K, int mode)
{
    extern __shared__ uint32_t smem_u[];

    const int tid  = threadIdx.x;
    const int warp = tid >> 5;
    const int lane = tid & 31;
    const int m0 = blockIdx.y * 128;
    const int n0 = blockIdx.x * 128;
    const int wm = (warp >> 1) * 32;
    const int wn = (warp & 1) * 64;
    const int grp = lane >> 2;
    const int tig = lane & 3;
    const uint32_t smbase = (uint32_t)__cvta_generic_to_shared(smem_u);

    const int aRow = wm + (lane & 7) + ((lane >> 3) & 1) * 8;
    const int aBlk = lane >> 4;
    const int bRow = wn + (lane & 7) + (lane >> 4) * 8;
    const int bBlk = (lane >> 3) & 1;

    float acc[2][8][4];
    #pragma unroll
    for (int mi = 0; mi < 2; mi++)
        #pragma unroll
        for (int ni = 0; ni < 8; ni++)
            #pragma unroll
            for (int c = 0; c < 4; c++) acc[mi][ni][c] = 0.f;

    const int KT = K >> 5;     // BK = 32

    #define LOAD_STAGE(s, k0)                                                          \
    {                                                                                  \
        _Pragma("unroll")                                                              \
        for (int r = 0; r < 2; r++) {                                                  \
            int idx = tid + r * 256;                                                   \
            int row = idx >> 2, c = idx & 3;                                           \
            uint32_t doff = ((s) * STG + row * PSTR + c * 4) * 4;                      \
            size_t aoff = (size_t)(m0 + row) * K + (k0) + c * 8;                       \
            size_t boff = (size_t)(n0 + row) * K + (k0) + c * 8;                       \
            cp_async16(smbase + (0 * 2 * STG) * 4 + doff, Ah + aoff);                  \
            cp_async16(smbase + (1 * 2 * STG) * 4 + doff, Al + aoff);                  \
            cp_async16(smbase + (2 * 2 * STG) * 4 + doff, Bh + boff);                  \
            cp_async16(smbase + (3 * 2 * STG) * 4 + doff, Bl + boff);                  \
        }                                                                              \
        cp_async_commit();                                                             \
    }

    LOAD_STAGE(0, 0)

    int buf = 0;
    for (int kt = 0; kt < KT; kt++) {
        cp_async_wait0();
        __syncthreads();
        if (kt + 1 < KT) {
            LOAD_STAGE(buf ^ 1, (kt + 1) << 5)
        }

        #pragma unroll
        for (int st = 0; st < 2; st++) {
            uint32_t ah_[2][4], al_[2][4];
            #pragma unroll
            for (int mi = 0; mi < 2; mi++) {
                uint32_t ad = smbase + (buf * STG + (aRow + mi * 16) * PSTR) * 4
                            + (st * 2 + aBlk) * 16;
                ldsm_x4(ah_[mi][0], ah_[mi][1], ah_[mi][2], ah_[mi][3], ad);
                ldsm_x4(al_[mi][0], al_[mi][1], al_[mi][2], al_[mi][3],
                        ad + 2 * STG * 4);
            }
            uint32_t bh_[8][2], bl_[8][2];
            #pragma unroll
            for (int t = 0; t < 4; t++) {
                uint32_t ad = smbase + (buf * STG + (bRow + t * 16) * PSTR) * 4
                            + (st * 2 + bBlk) * 16 + 4 * STG * 4;
                ldsm_x4(bh_[2*t][0], bh_[2*t][1], bh_[2*t+1][0], bh_[2*t+1][1], ad);
                ldsm_x4(bl_[2*t][0], bl_[2*t][1], bl_[2*t+1][0], bl_[2*t+1][1],
                        ad + 2 * STG * 4);
            }
            // term-major: spaces same-accumulator MMAs 16 apart
            #pragma unroll
            for (int mi = 0; mi < 2; mi++)
                #pragma unroll
                for (int ni = 0; ni < 8; ni++)
                    mma_bf16(acc[mi][ni], al_[mi][0], al_[mi][1], al_[mi][2],
                             al_[mi][3], bh_[ni][0], bh_[ni][1]);
            #pragma unroll
            for (int mi = 0; mi < 2; mi++)
                #pragma unroll
                for (int ni = 0; ni < 8; ni++)
                    mma_bf16(acc[mi][ni], ah_[mi][0], ah_[mi][1], ah_[mi][2],
                             ah_[mi][3], bl_[ni][0], bl_[ni][1]);
            #pragma unroll
            for (int mi = 0; mi < 2; mi++)
                #pragma unroll
                for (int ni = 0; ni < 8; ni++)
                    mma_bf16(acc[mi][ni], ah_[mi][0], ah_[mi][1], ah_[mi][2],
                             ah_[mi][3], bh_[ni][0], bh_[ni][1]);
        }
        __syncthreads();
        buf ^= 1;
    }

    // ---- epilogue ----
    #pragma unroll
    for (int mi = 0; mi < 2; mi++) {
        int row0 = m0 + wm + mi * 16 + grp;
        #pragma unroll
        for (int ni = 0; ni < 8; ni++) {
            int col = n0 + wn + ni * 8 + tig * 2;
            float b0 = bias[col], b1 = bias[col + 1];
            float v0 = acc[mi][ni][0] + b0;
            float v1 = acc[mi][ni][1] + b1;
            float v2 = acc[mi][ni][2] + b0;
            float v3 = acc[mi][ni][3] + b1;
            if (mode == 1) {
                v0 = 0.5f * v0 * (1.0f + erff(v0 * 0.70710678118654752f));
                v1 = 0.5f * v1 * (1.0f + erff(v1 * 0.70710678118654752f));
                v2 = 0.5f * v2 * (1.0f + erff(v2 * 0.70710678118654752f));
                v3 = 0.5f * v3 * (1.0f + erff(v3 * 0.70710678118654752f));
                size_t o0 = (size_t)row0 * N + col;
                size_t o1 = (size_t)(row0 + 8) * N + col;
                uint32_t ph, pl;
                packsplit(v0, v1, ph, pl);
                *(uint32_t*)(Ch + o0) = ph; *(uint32_t*)(Cl + o0) = pl;
                packsplit(v2, v3, ph, pl);
                *(uint32_t*)(Ch + o1) = ph; *(uint32_t*)(Cl + o1) = pl;
            } else {
                *(float2*)(Cf + (size_t)row0 * N + col)       = make_float2(v0, v1);
                *(float2*)(Cf + (size_t)(row0 + 8) * N + col) = make_float2(v2, v3);
            }
        }
    }
}

// ================= tensor-core local attention (mma.sync) =================
#define QSTR 36
#define ATT_SMEM ((2 * 128 * QSTR + 4 * 64 * QSTR + 64) * 4)

__global__ __launch_bounds__(256, 1) void attn_tc_kernel(
    const float* __restrict__ QKV, const int* __restrict__ amask,
    bf16* __restrict__ Ohi, bf16* __restrict__ Olo)
{
    extern __shared__ uint32_t sm[];
    const int OQH = 0;
    const int OQL = OQH + 128 * QSTR;
    const int OKH = OQL + 128 * QSTR;
    const int OKL = OKH + 64 * QSTR;
    const int OVH = OKL + 64 * QSTR;
    const int OVL = OVH + 64 * QSTR;
    const int OMF = OVL + 64 * QSTR;
    bf16* smb = (bf16*)sm;
    float* mf = (float*)(sm + OMF);

    const int q0 = blockIdx.x * 128;
    const int hh = blockIdx.y;
    const int b  = blockIdx.z;
    const int tid = threadIdx.x, warp = tid >> 5, lane = tid & 31;
    const int grp = lane >> 2, tig = lane & 3;
    const uint32_t base = (uint32_t)__cvta_generic_to_shared(sm);
    const unsigned FULL = 0xffffffffu;

    for (int idx = tid; idx < 128 * 64; idx += 256) {
        int r = idx >> 6, d = idx & 63;
        float x = QKV[(size_t)(b * S_ + q0 + r) * QKVS + hh * DH_ + d] * 0.125f;
        bf16 hi, lo; split_bf16(x, hi, lo);
        smb[OQH * 2 + r * (QSTR * 2) + d] = hi;
        smb[OQL * 2 + r * (QSTR * 2) + d] = lo;
    }
    __syncthreads();

    uint32_t qfh[4][4], qfl[4][4];
    {
        int arow = warp * 16 + (lane & 7) + ((lane >> 3) & 1) * 8;
        int ablk = lane >> 4;
        #pragma unroll
        for (int st = 0; st < 4; st++) {
            uint32_t ad = base + (OQH + arow * QSTR) * 4 + (st * 2 + ablk) * 16;
            ldsm_x4(qfh[st][0], qfh[st][1], qfh[st][2], qfh[st][3], ad);
            ldsm_x4(qfl[st][0], qfl[st][1], qfl[st][2], qfl[st][3],
                    ad + (OQL - OQH) * 4);
        }
    }

    float o[8][4];
    #pragma unroll
    for (int ni = 0; ni < 8; ni++)
        #pragma unroll
        for (int c = 0; c < 4; c++) o[ni][c] = 0.f;
    float m0 = -1e30f, m1 = -1e30f, l0 = 0.f, l1 = 0.f;

    const int brow = (lane & 7) + (lane >> 4) * 8;
    const int bblk = (lane >> 3) & 1;
    const int vrow = (lane & 7) + ((lane >> 3) & 1) * 8;
    const int vblk = lane >> 4;
    const int qg0 = q0 + warp * 16 + grp;
    const int qg1 = qg0 + 8;

    for (int kt = 0; kt < 10; kt++) {
        const int ks = q0 - 256 + kt * 64;
        if (ks + 64 <= 0 || ks >= S_) continue;
        __syncthreads();
        for (int idx = tid; idx < 64 * 64; idx += 256) {
            int c = idx >> 6, d = idx & 63;
            int kg = ks + c;
            bool in = (kg >= 0 && kg < S_);
            float kx = in ? QKV[(size_t)(b * S_ + kg) * QKVS + H_ + hh * DH_ + d] : 0.f;
            float vx = in ? QKV[(size_t)(b * S_ + kg) * QKVS + 2 * H_ + hh * DH_ + d] : 0.f;
            bf16 hi, lo;
            int ro = c * (QSTR * 2) + d;
            split_bf16(kx, hi, lo);
            smb[OKH * 2 + ro] = hi; smb[OKL * 2 + ro] = lo;
            split_bf16(vx, hi, lo);
            smb[OVH * 2 + ro] = hi; smb[OVL * 2 + ro] = lo;
        }
        if (tid < 64) {
            int kg = ks + tid;
            mf[tid] = (kg >= 0 && kg < S_ && amask[b * S_ + kg] > 0) ? 0.f : -1e9f;
        }
        __syncthreads();

        float s[8][4];
        #pragma unroll
        for (int ni = 0; ni < 8; ni++)
            #pragma unroll
            for (int c = 0; c < 4; c++) s[ni][c] = 0.f;
        #pragma unroll
        for (int st = 0; st < 4; st++) {
            uint32_t kbh[8][2], kbl[8][2];
            #pragma unroll
            for (int t = 0; t < 4; t++) {
                uint32_t ad = base + (OKH + (t * 16 + brow) * QSTR) * 4
                            + (st * 2 + bblk) * 16;
                ldsm_x4(kbh[2*t][0], kbh[2*t][1], kbh[2*t+1][0], kbh[2*t+1][1], ad);
                ldsm_x4(kbl[2*t][0], kbl[2*t][1], kbl[2*t+1][0], kbl[2*t+1][1],
                        ad + (OKL - OKH) * 4);
            }
            #pragma unroll
            for (int ni = 0; ni < 8; ni++)
                mma_bf16(s[ni], qfl[st][0], qfl[st][1], qfl[st][2], qfl[st][3],
                         kbh[ni][0], kbh[ni][1]);
            #pragma unroll
            for (int ni = 0; ni < 8; ni++)
                mma_bf16(s[ni], qfh[st][0], qfh[st][1], qfh[st][2], qfh[st][3],
                         kbl[ni][0], kbl[ni][1]);
            #pragma unroll
            for (int ni = 0; ni < 8; ni++)
                mma_bf16(s[ni], qfh[st][0], qfh[st][1], qfh[st][2], qfh[st][3],
                         kbh[ni][0], kbh[ni][1]);
        }

        float tmax0 = -1e30f, tmax1 = -1e30f;
        #pragma unroll
        for (int ni = 0; ni < 8; ni++) {
            int kl0 = ni * 8 + 2 * tig;
            float mv0 = mf[kl0], mv1 = mf[kl0 + 1];
            int kg0 = ks + kl0;
            int d00 = kg0 - qg0, d01 = d00 + 1;
            int d10 = kg0 - qg1, d11 = d10 + 1;
            float x0 = (d00 >= -WIN_ && d00 <= WIN_) ? s[ni][0] + mv0 : -1e9f;
            float x1 = (d01 >= -WIN_ && d01 <= WIN_) ? s[ni][1] + mv1 : -1e9f;
            float x2 = (d10 >= -WIN_ && d10 <= WIN_) ? s[ni][2] + mv0 : -1e9f;
            float x3 = (d11 >= -WIN_ && d11 <= WIN_) ? s[ni][3] + mv1 : -1e9f;
            s[ni][0] = x0; s[ni][1] = x1; s[ni][2] = x2; s[ni][3] = x3;
            tmax0 = fmaxf(tmax0, fmaxf(x0, x1));
            tmax1 = fmaxf(tmax1, fmaxf(x2, x3));
        }
        tmax0 = fmaxf(tmax0, __shfl_xor_sync(FULL, tmax0, 1));
        tmax0 = fmaxf(tmax0, __shfl_xor_sync(FULL, tmax0, 2));
        tmax1 = fmaxf(tmax1, __shfl_xor_sync(FULL, tmax1, 1));
        tmax1 = fmaxf(tmax1, __shfl_xor_sync(FULL, tmax1, 2));
        float mn0 = fmaxf(m0, tmax0), mn1 = fmaxf(m1, tmax1);
        float sc0 = __expf(m0 - mn0), sc1 = __expf(m1 - mn1);
        float ps0 = 0.f, ps1 = 0.f;
        #pragma unroll
        for (int ni = 0; ni < 8; ni++) {
            s[ni][0] = __expf(s[ni][0] - mn0);
            s[ni][1] = __expf(s[ni][1] - mn0);
            s[ni][2] = __expf(s[ni][2] - mn1);
            s[ni][3] = __expf(s[ni][3] - mn1);
            ps0 += s[ni][0] + s[ni][1];
            ps1 += s[ni][2] + s[ni][3];
        }
        ps0 += __shfl_xor_sync(FULL, ps0, 1);
        ps0 += __shfl_xor_sync(FULL, ps0, 2);
        ps1 += __shfl_xor_sync(FULL, ps1, 1);
        ps1 += __shfl_xor_sync(FULL, ps1, 2);
        l0 = l0 * sc0 + ps0;
        l1 = l1 * sc1 + ps1;
        m0 = mn0; m1 = mn1;
        #pragma unroll
        for (int ni = 0; ni < 8; ni++) {
            o[ni][0] *= sc0; o[ni][1] *= sc0;
            o[ni][2] *= sc1; o[ni][3] *= sc1;
        }

        uint32_t pah[4][4], pal[4][4];
        #pragma unroll
        for (int j = 0; j < 4; j++) {
            packsplit(s[2*j][0],   s[2*j][1],   pah[j][0], pal[j][0]);
            packsplit(s[2*j][2],   s[2*j][3],   pah[j][1], pal[j][1]);
            packsplit(s[2*j+1][0], s[2*j+1][1], pah[j][2], pal[j][2]);
            packsplit(s[2*j+1][2], s[2*j+1][3], pah[j][3], pal[j][3]);
        }

        #pragma unroll
        for (int j = 0; j < 4; j++) {
            uint32_t vbh[8][2], vbl[8][2];
            #pragma unroll
            for (int t = 0; t < 4; t++) {
                uint32_t ad = base + (OVH + (j * 16 + vrow) * QSTR) * 4
                            + (2 * t + vblk) * 16;
                ldsm_x4_t(vbh[2*t][0], vbh[2*t][1], vbh[2*t+1][0], vbh[2*t+1][1], ad);
                ldsm_x4_t(vbl[2*t][0], vbl[2*t][1], vbl[2*t+1][0], vbl[2*t+1][1],
                          ad + (OVL - OVH) * 4);
            }
            #pragma unroll
            for (int ni = 0; ni < 8; ni++)
                mma_bf16(o[ni], pal[j][0], pal[j][1], pal[j][2], pal[j][3],
                         vbh[ni][0], vbh[ni][1]);
            #pragma unroll
            for (int ni = 0; ni < 8; ni++)
                mma_bf16(o[ni], pah[j][0], pah[j][1], pah[j][2], pah[j][3],
                         vbl[ni][0], vbl[ni][1]);
            #pragma unroll
            for (int ni = 0; ni < 8; ni++)
                mma_bf16(o[ni], pah[j][0], pah[j][1], pah[j][2], pah[j][3],
                         vbh[ni][0], vbh[ni][1]);
        }
    }

    float inv0 = 1.f / l0, inv1 = 1.f / l1;
    #pragma unroll
    for (int ni = 0; ni < 8; ni++) {
        int dcol = hh * DH_ + ni * 8 + 2 * tig;
        size_t o0 = (size_t)(b * S_ + qg0) * H_ + dcol;
        size_t o1 = (size_t)(b * S_ + qg1) * H_ + dcol;
        uint32_t ph, pl;
        packsplit(o[ni][0] * inv0, o[ni][1] * inv0, ph, pl);
        *(uint32_t*)(Ohi + o0) = ph;
        *(uint32_t*)(Olo + o0) = pl;
        packsplit(o[ni][2] * inv1, o[ni][3] * inv1, ph, pl);
        *(uint32_t*)(Ohi + o1) = ph;
        *(uint32_t*)(Olo + o1) = pl;
    }
}

// ---------------- pooling head ----------------
__global__ __launch_bounds__(256) void attn_score_kernel(
    const float* __restrict__ h, const float* __restrict__ aw, float* __restrict__ sc)
{
    int t = blockIdx.x;
    int tid = threadIdx.x;
    float acc = 0.f;
    #pragma unroll
    for (int i = 0; i < 3; i++) {
        int c = tid + i * 256;
        acc += h[(size_t)t * H_ + c] * aw[c];
    }
    float s = block_reduce_sum(acc);
    if (tid == 0) sc[t] = s;
}

__global__ __launch_bounds__(256) void softmax_s_kernel(
    const float* __restrict__ sc, float* __restrict__ pr)
{
    int b = blockIdx.x;
    int tid = threadIdx.x;
    float v[4];
    float mx = -1e30f;
    #pragma unroll
    for (int i = 0; i < 4; i++) {
        v[i] = sc[b * S_ + tid + i * 256];
        mx = fmaxf(mx, v[i]);
    }
    mx = block_reduce_max(mx);
    float e[4], ps = 0.f;
    #pragma unroll
    for (int i = 0; i < 4; i++) { e[i] = __expf(v[i] - mx); ps += e[i]; }
    float tot = block_reduce_sum(ps);
    float inv = 1.f / tot;
    #pragma unroll
    for (int i = 0; i < 4; i++) pr[b * S_ + tid + i * 256] = e[i] * inv;
}

__global__ __launch_bounds__(256) void pool_kernel(
    const float* __restrict__ h, const float* __restrict__ pr, float* __restrict__ pooled)
{
    int d = blockIdx.x * 256 + threadIdx.x;
    int b = blockIdx.y;
    float acc = 0.f;
    for (int s = 0; s < S_; s++) {
        acc += h[((size_t)(b * S_ + s)) * H_ + d] * pr[b * S_ + s];
    }
    pooled[b * H_ + d] = acc;
}

__global__ __launch_bounds__(256) void final_kernel(
    const float* __restrict__ pooled, const float* __restrict__ Wc,
    const float* __restrict__ bc, float* __restrict__ out)
{
    int b = blockIdx.x;
    int tid = threadIdx.x;
    float acc = 0.f;
    #pragma unroll
    for (int i = 0; i < 3; i++) {
        int c = tid + i * 256;
        acc += pooled[b * H_ + c] * Wc[c];
    }
    float s = block_reduce_sum(acc);
    if (tid == 0) out[b] = s + bc[0];
}

// ---------------- host launcher ----------------
extern "C" void kernel_launch(void* const* d_in, const int* in_sizes, int n_in,
                              void* d_out, int out_size)
{
    (void)in_sizes; (void)n_in; (void)out_size;
    const float* WE   = (const float*)d_in[0];
    const float* PE   = (const float*)d_in[1];
    const float* Eg   = (const float*)d_in[2];
    const float* Eb   = (const float*)d_in[3];
    const float* Wq   = (const float*)d_in[4];
    const float* bq   = (const float*)d_in[5];
    const float* Wk   = (const float*)d_in[6];
    const float* bk   = (const float*)d_in[7];
    const float* Wv   = (const float*)d_in[8];
    const float* bv   = (const float*)d_in[9];
    const float* Wo   = (const float*)d_in[10];
    const float* bo   = (const float*)d_in[11];
    const float* g1   = (const float*)d_in[12];
    const float* beta1= (const float*)d_in[13];
    const float* W1   = (const float*)d_in[14];
    const float* b1   = (const float*)d_in[15];
    const float* W2   = (const float*)d_in[16];
    const float* b2   = (const float*)d_in[17];
    const float* g2   = (const float*)d_in[18];
    const float* beta2= (const float*)d_in[19];
    const float* aw   = (const float*)d_in[20];
    const float* Wc   = (const float*)d_in[21];
    const float* bc   = (const float*)d_in[22];
    const int*   ids  = (const int*)d_in[23];
    const int*   am   = (const int*)d_in[24];
    float* out = (float*)d_out;

    bf16 *wqkv_hi, *wqkv_lo, *wot_hi, *wot_lo, *w1t_hi, *w1t_lo, *w2t_hi, *w2t_lo;
    bf16 *h_hi, *h_lo, *a_hi, *a_lo, *f_hi, *f_lo;
    float *bqkv, *h, *qkv, *r, *sc, *pr, *pooled;
    cudaGetSymbolAddress((void**)&wqkv_hi, g_wqkv_hi);
    cudaGetSymbolAddress((void**)&wqkv_lo, g_wqkv_lo);
    cudaGetSymbolAddress((void**)&wot_hi,  g_wot_hi);
    cudaGetSymbolAddress((void**)&wot_lo,  g_wot_lo);
    cudaGetSymbolAddress((void**)&w1t_hi,  g_w1t_hi);
    cudaGetSymbolAddress((void**)&w1t_lo,  g_w1t_lo);
    cudaGetSymbolAddress((void**)&w2t_hi,  g_w2t_hi);
    cudaGetSymbolAddress((void**)&w2t_lo,  g_w2t_lo);
    cudaGetSymbolAddress((void**)&bqkv,    g_bqkv);
    cudaGetSymbolAddress((void**)&h,       g_h);
    cudaGetSymbolAddress((void**)&h_hi,    g_h_hi);
    cudaGetSymbolAddress((void**)&h_lo,    g_h_lo);
    cudaGetSymbolAddress((void**)&qkv,     g_qkv);
    cudaGetSymbolAddress((void**)&a_hi,    g_a_hi);
    cudaGetSymbolAddress((void**)&a_lo,    g_a_lo);
    cudaGetSymbolAddress((void**)&f_hi,    g_f_hi);
    cudaGetSymbolAddress((void**)&f_lo,    g_f_lo);
    cudaGetSymbolAddress((void**)&r,       g_r);
    cudaGetSymbolAddress((void**)&sc,      g_sc);
    cudaGetSymbolAddress((void**)&pr,      g_pr);
    cudaGetSymbolAddress((void**)&pooled,  g_pool);

    cudaFuncSetAttribute(tgemm_kernel,
                         cudaFuncAttributeMaxDynamicSharedMemorySize, 8 * STG * 4);
    cudaFuncSetAttribute(attn_tc_kernel,
                         cudaFuncAttributeMaxDynamicSharedMemorySize, ATT_SMEM);

    // ---- pre-pass: exactly 5 launches so ncu (-s 5) lands on first GEMM ----
    dim3 wb(256);
    wsplit_qkv_kernel<<<dim3(H_ / 32, H_ / 32, 3 * L_), wb>>>(Wq, Wk, Wv,
                                                              wqkv_hi, wqkv_lo);
    wsplit_kernel<<<dim3(H_ / 32, H_ / 32, L_), wb>>>(Wo, wot_hi, wot_lo, H_, H_,
        (size_t)H_ * H_, (size_t)H_ * H_);
    wsplit_kernel<<<dim3(FF_ / 32, H_ / 32, L_), wb>>>(W1, w1t_hi, w1t_lo, H_, FF_,
        (size_t)H_ * FF_, (size_t)FF_ * H_);
    wsplit_kernel<<<dim3(H_ / 32, FF_ / 32, L_), wb>>>(W2, w2t_hi, w2t_lo, FF_, H_,
        (size_t)FF_ * H_, (size_t)H_ * FF_);
    embed_ln_kernel<<<BS_ + L_, 256>>>(WE, PE, Eg, Eb, ids, h, h_hi, h_lo,
                                       bq, bk, bv, bqkv);

    const size_t SMEMB = 8 * STG * 4;
    dim3 gQKV(QKVS / 128, BS_ / 128);
    dim3 gO(H_ / 128, BS_ / 128);
    dim3 gW1(FF_ / 128, BS_ / 128);
    dim3 gattn(S_ / 128, NH_, B_);

    for (int l = 0; l < L_; l++) {
        tgemm_kernel<<<gQKV, 256, SMEMB>>>(h_hi, h_lo,
            wqkv_hi + (size_t)l * QKVS * H_, wqkv_lo + (size_t)l * QKVS * H_,
            bqkv + l * QKVS, qkv, nullptr, nullptr, BS_, QKVS, H_, 0);

        attn_tc_kernel<<<gattn, 256, ATT_SMEM>>>(qkv, am, a_hi, a_lo);

        tgemm_kernel<<<gO, 256, SMEMB>>>(a_hi, a_lo,
            wot_hi + (size_t)l * H_ * H_, wot_lo + (size_t)l * H_ * H_,
            bo + l * H_, r, nullptr, nullptr, BS_, H_, H_, 0);
        add_ln_kernel<<<BS_, 256>>>(h, r, g1 + l * H_, beta1 + l * H_, h_hi, h_lo);

        tgemm_kernel<<<gW1, 256, SMEMB>>>(h_hi, h_lo,
            w1t_hi + (size_t)l * FF_ * H_, w1t_lo + (size_t)l * FF_ * H_,
            b1 + l * FF_, nullptr, f_hi, f_lo, BS_, FF_, H_, 1);

        tgemm_kernel<<<gO, 256, SMEMB>>>(f_hi, f_lo,
            w2t_hi + (size_t)l * H_ * FF_, w2t_lo + (size_t)l * H_ * FF_,
            b2 + l * H_, r, nullptr, nullptr, BS_, H_, FF_, 0);
        add_ln_kernel<<<BS_, 256>>>(h, r, g2 + l * H_, beta2 + l * H_, h_hi, h_lo);
    }

    attn_score_kernel<<<BS_, 256>>>(h, aw, sc);
    softmax_s_kernel<<<B_, 256>>>(sc, pr);
    pool_kernel<<<dim3(H_ / 256, B_), 256>>>(h, pr, pooled);
    final_kernel<<<B_, 256>>>(pooled, Wc, bc, out);
}